// round 12
// baseline (speedup 1.0000x reference)
#include <cuda_runtime.h>
#include <math.h>

#define T_STEPS 64
#define B_ 128
#define H_ 256
#define C_ 256
#define K_ 8
#define L_ 3
#define BK 1024
#define NEGV (-1e30f)

// ------------------------- device scratch (static, no allocs) ---------------
__device__ float g_WpT[H_ * C_];            // Wp transposed: [i][c]
__device__ float g_P0[C_ * 4 * H_];         // emb @ W_ih0^T + b_ih0 + b_hh0
__device__ float g_state[BK * H_];          // [B*K, H]
__device__ float g_h[2][L_][BK * H_];       // ping-pong hidden
__device__ float g_c[2][L_][BK * H_];       // ping-pong cell
__device__ float g_prefix[B_ * K_];
__device__ int   g_choices[B_ * K_ * T_STEPS];
__device__ int   g_src[BK];                 // gather source row (b*K + prev)
__device__ int   g_cls[BK];                 // chosen class per new beam row

// ------------------------- f32x2 packed helpers (sm_103a FFMA2) -------------
typedef unsigned long long u64;

__device__ __forceinline__ u64 fma2(u64 a, u64 b, u64 c) {
    u64 d;
    asm("fma.rn.f32x2 %0, %1, %2, %3;" : "=l"(d) : "l"(a), "l"(b), "l"(c));
    return d;
}
__device__ __forceinline__ u64 bcast2(float x) {
    u64 d; unsigned xi = __float_as_uint(x);
    asm("mov.b64 %0, {%1, %1};" : "=l"(d) : "r"(xi));
    return d;
}
__device__ __forceinline__ float lo2(u64 v) { return __uint_as_float((unsigned)v); }
__device__ __forceinline__ float hi2(u64 v) { return __uint_as_float((unsigned)(v >> 32)); }

// ------------------------- precise, fast-math-immune transcendentals --------
__device__ __forceinline__ float f_exp(float x) {
    const float LOG2E  = 1.4426950408889634f;
    const float LN2_HI = 0.693145751953125f;
    const float LN2_LO = 1.4286067653e-06f;
    float n = rintf(x * LOG2E);
    float r = fmaf(-n, LN2_HI, x);
    r = fmaf(-n, LN2_LO, r);
    float p = 1.9841269841e-4f;
    p = fmaf(p, r, 1.3888888889e-3f);
    p = fmaf(p, r, 8.3333333333e-3f);
    p = fmaf(p, r, 4.1666666667e-2f);
    p = fmaf(p, r, 1.6666666667e-1f);
    p = fmaf(p, r, 0.5f);
    p = fmaf(p, r, 1.0f);
    p = fmaf(p, r, 1.0f);
    int ni = (int)n;
    if (ni < -250) return 0.0f;
    if (ni >  250) ni = 250;
    int e1 = ni >> 1;
    int e2 = ni - e1;
    float s1 = __int_as_float((e1 + 127) << 23);
    float s2 = __int_as_float((e2 + 127) << 23);
    return p * s1 * s2;
}

__device__ __forceinline__ float f_tanh(float x) {
    float ax = fabsf(x);
    float t;
    if (ax < 0.25f) {
        float x2 = ax * ax;
        float p = 2.1869488536e-2f;
        p = fmaf(p, x2, -5.3968253968e-2f);
        p = fmaf(p, x2, 1.3333333333e-1f);
        p = fmaf(p, x2, -3.3333333333e-1f);
        t = fmaf(p * x2, ax, ax);
    } else {
        float e = f_exp(2.0f * ax);
        t = 1.0f - __fdiv_rn(2.0f, e + 1.0f);
    }
    return copysignf(t, x);
}

__device__ __forceinline__ float f_sig(float x) {
    return __fdiv_rn(1.0f, 1.0f + f_exp(-x));
}

// ------------------------- fused init: transpose + misc + P0 ----------------
__global__ __launch_bounds__(256) void k_init_combo(const float* __restrict__ x,
                                                    const float* __restrict__ Wp,
                                                    const float* __restrict__ emb,
                                                    const float* __restrict__ Wih0,
                                                    const float* __restrict__ bih0,
                                                    const float* __restrict__ bhh0) {
    int blk = blockIdx.x;
    if (blk < 1024) {
        int idx = blk * 256 + threadIdx.x;   // BK*H_ total
        int row = idx >> 8;
        int j = idx & 255;
        int b = row >> 3;
        g_state[idx] = x[b * H_ + j];
        if (idx < B_ * K_) g_prefix[idx] = ((idx & 7) == 0) ? 0.f : NEGV;
        if (idx < B_ * K_ * T_STEPS) g_choices[idx] = 0;
        return;
    }
    if (blk < 1280) {
        int idx = (blk - 1024) * 256 + threadIdx.x;   // H_*C_ total
        int i = idx >> 8, c = idx & 255;
        g_WpT[i * C_ + c] = Wp[c * H_ + i];
        return;
    }
    __shared__ float se[H_];
    int cidx = blk - 1280;
    se[threadIdx.x] = emb[cidx * H_ + threadIdx.x];
    __syncthreads();
    int t = threadIdx.x;
#pragma unroll
    for (int q = 0; q < 4; q++) {
        int n = q * H_ + t;
        const float4* wr = (const float4*)(Wih0 + (size_t)n * H_);
        float acc = 0.f;
#pragma unroll 8
        for (int k4 = 0; k4 < H_ / 4; k4++) {
            float4 w = wr[k4];
            float4 e = *(const float4*)&se[k4 * 4];
            acc += w.x * e.x + w.y * e.y + w.z * e.z + w.w * e.w;
        }
        g_P0[(size_t)cidx * (4 * H_) + n] = acc + bih0[n] + bhh0[n];
    }
}

// ------------------------- init LSTM, all 3 layers in one kernel ------------
__global__ __launch_bounds__(256) void k_init_lstm_all(const float* __restrict__ x,
                                                       const float* __restrict__ W_ih,
                                                       const float* __restrict__ b_ih,
                                                       const float* __restrict__ b_hh) {
    __shared__ float si[H_];
    int b = blockIdx.x;
    int t = threadIdx.x;
    const int WSTR = 4 * H_ * H_;
    const int BSTR = 4 * H_;
    for (int layer = 0; layer < L_; layer++) {
        const float* Wih = W_ih + (size_t)layer * WSTR;
        const float* bih = b_ih + (size_t)layer * BSTR;
        const float* bhh = b_hh + (size_t)layer * BSTR;
        const float* in = (layer == 0) ? (x + (size_t)b * H_)
                                       : (&g_h[0][layer - 1][0] + (size_t)(b * K_) * H_);
        si[t] = in[t];
        __syncthreads();
        float g4[4];
#pragma unroll
        for (int q = 0; q < 4; q++) {
            int n = q * H_ + t;
            const float4* wr = (const float4*)(Wih + (size_t)n * H_);
            float acc = 0.f;
#pragma unroll 8
            for (int k4 = 0; k4 < H_ / 4; k4++) {
                float4 w = wr[k4];
                float4 e = *(const float4*)&si[k4 * 4];
                acc += w.x * e.x + w.y * e.y + w.z * e.z + w.w * e.w;
            }
            g4[q] = acc + bih[n] + bhh[n];
        }
        float cn = f_sig(g4[0]) * f_tanh(g4[2]);
        float hn = f_sig(g4[3]) * f_tanh(cn);
#pragma unroll
        for (int kb = 0; kb < K_; kb++) {
            g_h[0][layer][((size_t)b * K_ + kb) * H_ + t] = hn;
            g_c[0][layer][((size_t)b * K_ + kb) * H_ + t] = cn;
        }
        __syncthreads();
    }
}

// ------------------------- projection + log_softmax + top-K -----------------
__global__ __launch_bounds__(256) void k_proj(const float* __restrict__ bp, int t) {
    __shared__ __align__(16) float s_state[K_][H_];
    __shared__ float s_pref[K_];
    __shared__ float s_red[8][K_];
    __shared__ float s_max[K_];
    __shared__ float s_lsum[K_];
    __shared__ float s_redv[8];
    __shared__ int   s_redi[8];
    __shared__ float s_topv[K_];
    __shared__ int   s_topi[K_];
    __shared__ int   s_prev[K_];
    __shared__ int   s_clss[K_];
    __shared__ int   s_ch[K_ * T_STEPS];

    int b = blockIdx.x;
    int tid = threadIdx.x;
    int warp = tid >> 5, lane = tid & 31;

    for (int u = tid; u < K_ * H_; u += 256)
        ((float*)s_state)[u] = g_state[(size_t)b * K_ * H_ + u];
    if (tid < K_) s_pref[tid] = g_prefix[b * K_ + tid];
    __syncthreads();

    int c = tid;
    float acc[K_];
#pragma unroll
    for (int k = 0; k < K_; k++) acc[k] = 0.f;
    for (int i0 = 0; i0 < H_; i0 += 4) {
        float4 sv[K_];
#pragma unroll
        for (int k = 0; k < K_; k++) sv[k] = *(const float4*)&s_state[k][i0];
        float w0 = g_WpT[(i0 + 0) * C_ + c];
        float w1 = g_WpT[(i0 + 1) * C_ + c];
        float w2 = g_WpT[(i0 + 2) * C_ + c];
        float w3 = g_WpT[(i0 + 3) * C_ + c];
#pragma unroll
        for (int k = 0; k < K_; k++) acc[k] += sv[k].x * w0;
#pragma unroll
        for (int k = 0; k < K_; k++) acc[k] += sv[k].y * w1;
#pragma unroll
        for (int k = 0; k < K_; k++) acc[k] += sv[k].z * w2;
#pragma unroll
        for (int k = 0; k < K_; k++) acc[k] += sv[k].w * w3;
    }
    float bb = bp[c];
#pragma unroll
    for (int k = 0; k < K_; k++) acc[k] += bb;

    // per-beam max
    {
        float m[K_];
#pragma unroll
        for (int k = 0; k < K_; k++) {
            float v = acc[k];
            for (int o = 16; o; o >>= 1) v = fmaxf(v, __shfl_xor_sync(0xffffffffu, v, o));
            m[k] = v;
        }
        if (lane == 0)
#pragma unroll
            for (int k = 0; k < K_; k++) s_red[warp][k] = m[k];
        __syncthreads();
        if (tid < K_) {
            float v = s_red[0][tid];
            for (int w2 = 1; w2 < 8; w2++) v = fmaxf(v, s_red[w2][tid]);
            s_max[tid] = v;
        }
        __syncthreads();
    }
    float mx[K_];
#pragma unroll
    for (int k = 0; k < K_; k++) mx[k] = s_max[k];
    // per-beam sum of exp (precise exp)
    {
        float s[K_];
#pragma unroll
        for (int k = 0; k < K_; k++) {
            float v = f_exp(acc[k] - mx[k]);
            for (int o = 16; o; o >>= 1) v += __shfl_xor_sync(0xffffffffu, v, o);
            s[k] = v;
        }
        __syncthreads();
        if (lane == 0)
#pragma unroll
            for (int k = 0; k < K_; k++) s_red[warp][k] = s[k];
        __syncthreads();
        if (tid < K_) {
            float v = 0.f;
            for (int w2 = 0; w2 < 8; w2++) v += s_red[w2][tid];
            s_lsum[tid] = (float)log((double)v);   // precise log
        }
        __syncthreads();
    }
    float jt[K_];
#pragma unroll
    for (int k = 0; k < K_; k++) jt[k] = s_pref[k] + ((acc[k] - mx[k]) - s_lsum[k]);

    // iterated block argmax (ties -> lowest flat idx, matching jax top_k)
    for (int it = 0; it < K_; it++) {
        float bv = -INFINITY;
        int bi = 0x7fffffff;
#pragma unroll
        for (int k = 0; k < K_; k++) {
            if (jt[k] > bv) { bv = jt[k]; bi = k * C_ + c; }
        }
        for (int o = 16; o; o >>= 1) {
            float ov = __shfl_xor_sync(0xffffffffu, bv, o);
            int   oi = __shfl_xor_sync(0xffffffffu, bi, o);
            if (ov > bv || (ov == bv && oi < bi)) { bv = ov; bi = oi; }
        }
        if (lane == 0) { s_redv[warp] = bv; s_redi[warp] = bi; }
        __syncthreads();
        if (tid == 0) {
            float fv = s_redv[0]; int fi = s_redi[0];
            for (int w2 = 1; w2 < 8; w2++)
                if (s_redv[w2] > fv || (s_redv[w2] == fv && s_redi[w2] < fi)) {
                    fv = s_redv[w2]; fi = s_redi[w2];
                }
            s_topv[it] = fv; s_topi[it] = fi;
        }
        __syncthreads();
        int sel = s_topi[it];
        if ((sel & (C_ - 1)) == c) jt[sel >> 8] = -INFINITY;
    }

    if (tid < K_) {
        int sel = s_topi[tid];
        int prev = sel >> 8;
        int cls = sel & (C_ - 1);
        g_prefix[b * K_ + tid] = s_topv[tid];
        g_src[b * K_ + tid] = b * K_ + prev;
        g_cls[b * K_ + tid] = cls;
        s_prev[tid] = prev;
        s_clss[tid] = cls;
    }
    __syncthreads();
    for (int u = tid; u < K_ * T_STEPS; u += 256) {
        int kq = u >> 6, tt = u & 63;
        s_ch[u] = g_choices[(b * K_ + s_prev[kq]) * T_STEPS + tt];
    }
    __syncthreads();
    for (int u = tid; u < K_ * T_STEPS; u += 256) {
        int kq = u >> 6, tt = u & 63;
        g_choices[(b * K_ + kq) * T_STEPS + tt] = (tt == t) ? s_clss[kq] : s_ch[u];
    }
}

// ------------------------- LSTM layer GEMM + gates --------------------------
// Tile 128 rows x 64 gate-cols, 256 threads (R7 shape). Lane-flip mainloop:
// f32x2 lanes = two adjacent rows of ONE gate. A consumed as u64 row-pairs
// straight from As (no MOVs); W stored PRE-DUPLICATED in smem (u64 both
// halves = W[n][k]) and consumed as ulonglong2 (no MOVs). Per-output scalar
// FMA chain (k ascending) unchanged -> bit-identical to rounds 6-11.
template <int LAYER>
__global__ __launch_bounds__(256) void k_lstm(const float* __restrict__ Wih,
                                              const float* __restrict__ Whh,
                                              const float* __restrict__ bih,
                                              const float* __restrict__ bhh,
                                              const float* __restrict__ x,
                                              int rb, int t_next) {
    __shared__ __align__(16) float As[2][16][128];
    __shared__ __align__(16) u64 Ws2[2][16][64];
    __shared__ int s_src[128];
    __shared__ int s_cls[128];

    const float* hcur = g_h[rb][LAYER];
    const float* ccur = g_c[rb][LAYER];
    float* hnxt = g_h[1 - rb][LAYER];
    float* cnxt = g_c[1 - rb][LAYER];
    const float* inp = (LAYER == 0) ? (const float*)0 : g_h[1 - rb][LAYER - 1];

    int tid = threadIdx.x;
    int rBase = blockIdx.x * 128;
    int jBase = blockIdx.y * 16;

    if (tid < 128) {
        s_src[tid] = g_src[rBase + tid];
        if (LAYER == 0) s_cls[tid] = g_cls[rBase + tid];
    }
    __syncthreads();

    int arow = tid >> 1;            // 0..127: local A row
    int akq  = (tid & 1) * 8;       // k offset within 16-tile (0 or 8)
    int wrow = tid >> 2;            // 0..63: local W col (n_l = j_local*4+gate)
    int wkq  = (tid & 3) * 4;       // k offset (0,4,8,12)

    const float* aHid = hcur + (size_t)s_src[arow] * H_;
    const float* aIn  = (LAYER == 0) ? (const float*)0
                                     : inp + (size_t)(rBase + arow) * H_;
    const size_t wgrow = (size_t)((wrow & 3) * H_ + jBase + (wrow >> 2)) * H_;
    const float* wiP = Wih + wgrow;
    const float* whP = Whh + wgrow;

    const int KSTART = (LAYER == 0) ? 256 : 0;
    const int NT = (512 - KSTART) / 16;

    int tx = tid & 15, ty = tid >> 4;

    // acc[p][g]: row pair p (rows ty*8+2p, +2p+1) x gate g
    u64 acc[4][4];
#pragma unroll
    for (int p = 0; p < 4; p++)
#pragma unroll
        for (int gq = 0; gq < 4; gq++) acc[p][gq] = 0ull;

    float4 a0, a1, w0;
    {
        int k = KSTART + akq;
        const float* p = (LAYER > 0 && k < 256) ? (aIn + k) : (aHid + (k - 256));
        a0 = *(const float4*)p; a1 = *(const float4*)(p + 4);
        int kw = KSTART + wkq;
        const float* q = (LAYER > 0 && kw < 256) ? (wiP + kw) : (whP + (kw - 256));
        w0 = *(const float4*)q;
    }
    {
        As[0][akq + 0][arow] = a0.x; As[0][akq + 1][arow] = a0.y;
        As[0][akq + 2][arow] = a0.z; As[0][akq + 3][arow] = a0.w;
        As[0][akq + 4][arow] = a1.x; As[0][akq + 5][arow] = a1.y;
        As[0][akq + 6][arow] = a1.z; As[0][akq + 7][arow] = a1.w;
        Ws2[0][wkq + 0][wrow] = bcast2(w0.x);
        Ws2[0][wkq + 1][wrow] = bcast2(w0.y);
        Ws2[0][wkq + 2][wrow] = bcast2(w0.z);
        Ws2[0][wkq + 3][wrow] = bcast2(w0.w);
    }
    __syncthreads();

    for (int kt = 0; kt < NT; kt++) {
        int buf = kt & 1;
        bool more = (kt + 1 < NT);
        if (more) {
            int k = KSTART + (kt + 1) * 16 + akq;
            const float* p = (LAYER > 0 && k < 256) ? (aIn + k) : (aHid + (k - 256));
            a0 = *(const float4*)p; a1 = *(const float4*)(p + 4);
            int kw = KSTART + (kt + 1) * 16 + wkq;
            const float* q = (LAYER > 0 && kw < 256) ? (wiP + kw) : (whP + (kw - 256));
            w0 = *(const float4*)q;
        }
#pragma unroll
        for (int kk = 0; kk < 16; kk++) {
            // rows ty*8..ty*8+7 as 4 u64 row-pairs (direct reinterpret of As)
            ulonglong2 aA = *(const ulonglong2*)&As[buf][kk][ty * 8];
            ulonglong2 aB = *(const ulonglong2*)&As[buf][kk][ty * 8 + 4];
            // gates 0..3 of j = jBase+tx, pre-duplicated u64
            ulonglong2 wA = *(const ulonglong2*)&Ws2[buf][kk][tx * 4];
            ulonglong2 wB = *(const ulonglong2*)&Ws2[buf][kk][tx * 4 + 2];
            acc[0][0] = fma2(aA.x, wA.x, acc[0][0]); acc[0][1] = fma2(aA.x, wA.y, acc[0][1]);
            acc[0][2] = fma2(aA.x, wB.x, acc[0][2]); acc[0][3] = fma2(aA.x, wB.y, acc[0][3]);
            acc[1][0] = fma2(aA.y, wA.x, acc[1][0]); acc[1][1] = fma2(aA.y, wA.y, acc[1][1]);
            acc[1][2] = fma2(aA.y, wB.x, acc[1][2]); acc[1][3] = fma2(aA.y, wB.y, acc[1][3]);
            acc[2][0] = fma2(aB.x, wA.x, acc[2][0]); acc[2][1] = fma2(aB.x, wA.y, acc[2][1]);
            acc[2][2] = fma2(aB.x, wB.x, acc[2][2]); acc[2][3] = fma2(aB.x, wB.y, acc[2][3]);
            acc[3][0] = fma2(aB.y, wA.x, acc[3][0]); acc[3][1] = fma2(aB.y, wA.y, acc[3][1]);
            acc[3][2] = fma2(aB.y, wB.x, acc[3][2]); acc[3][3] = fma2(aB.y, wB.y, acc[3][3]);
        }
        if (more) {
            int nb = buf ^ 1;
            As[nb][akq + 0][arow] = a0.x; As[nb][akq + 1][arow] = a0.y;
            As[nb][akq + 2][arow] = a0.z; As[nb][akq + 3][arow] = a0.w;
            As[nb][akq + 4][arow] = a1.x; As[nb][akq + 5][arow] = a1.y;
            As[nb][akq + 6][arow] = a1.z; As[nb][akq + 7][arow] = a1.w;
            Ws2[nb][wkq + 0][wrow] = bcast2(w0.x);
            Ws2[nb][wkq + 1][wrow] = bcast2(w0.y);
            Ws2[nb][wkq + 2][wrow] = bcast2(w0.z);
            Ws2[nb][wkq + 3][wrow] = bcast2(w0.w);
        }
        __syncthreads();
    }

    // ---- epilogue (expressions identical to rounds 6-11) ----
    int j = jBase + tx;
    float bias[4];
    if (LAYER > 0) {
#pragma unroll
        for (int q = 0; q < 4; q++) bias[q] = bih[q * H_ + j] + bhh[q * H_ + j];
    }
#pragma unroll
    for (int r = 0; r < 8; r++) {
        int p = r >> 1;
        int hiLane = r & 1;
        int rl = ty * 8 + r;
        int row_g = rBase + rl;
        int b = row_g >> 3;
        float gi = hiLane ? hi2(acc[p][0]) : lo2(acc[p][0]);
        float gf = hiLane ? hi2(acc[p][1]) : lo2(acc[p][1]);
        float gg = hiLane ? hi2(acc[p][2]) : lo2(acc[p][2]);
        float go = hiLane ? hi2(acc[p][3]) : lo2(acc[p][3]);
        if (LAYER == 0) {
            const float* p0 = g_P0 + (size_t)s_cls[rl] * (4 * H_);
            gi += p0[0 * H_ + j]; gf += p0[1 * H_ + j];
            gg += p0[2 * H_ + j]; go += p0[3 * H_ + j];
        } else {
            gi += bias[0]; gf += bias[1]; gg += bias[2]; go += bias[3];
        }
        float cold = ccur[(size_t)s_src[rl] * H_ + j];
        float cn = f_sig(gf) * cold + f_sig(gi) * f_tanh(gg);
        float hn = f_sig(go) * f_tanh(cn);
        cnxt[(size_t)row_g * H_ + j] = cn;
        hnxt[(size_t)row_g * H_ + j] = hn;
        if (LAYER == 2)
            g_state[(size_t)row_g * H_ + j] = hn + x[(size_t)t_next * B_ * H_ + b * H_ + j];
    }
}

// ------------------------- output ------------------------------------------
__global__ void k_out(float* __restrict__ out, int n) {
    int i = blockIdx.x * 256 + threadIdx.x;
    if (i >= n) return;
    if (i < B_ * K_ * T_STEPS) out[i] = (float)g_choices[i];
    else if (i < B_ * K_ * T_STEPS + B_ * K_) out[i] = g_prefix[i - B_ * K_ * T_STEPS];
    else out[i] = 0.f;
}

// ------------------------- host --------------------------------------------
extern "C" void kernel_launch(void* const* d_in, const int* in_sizes, int n_in,
                              void* d_out, int out_size) {
    const float* x    = (const float*)d_in[0];
    const float* emb  = (const float*)d_in[1];
    const float* W_ih = (const float*)d_in[2];
    const float* W_hh = (const float*)d_in[3];
    const float* b_ih = (const float*)d_in[4];
    const float* b_hh = (const float*)d_in[5];
    const float* Wp   = (const float*)d_in[6];
    const float* bp   = (const float*)d_in[7];

    const int WSTRIDE = 4 * H_ * H_;
    const int BSTRIDE = 4 * H_;

    k_init_combo<<<1536, 256>>>(x, Wp, emb, W_ih, b_ih, b_hh);
    k_init_lstm_all<<<B_, 256>>>(x, W_ih, b_ih, b_hh);

    dim3 g(8, 16);
    for (int t = 0; t < T_STEPS; t++) {
        int rb = t & 1;
        int t_next = (t + 1 < T_STEPS) ? (t + 1) : (T_STEPS - 1);
        k_proj<<<B_, 256>>>(bp, t);
        k_lstm<0><<<g, 256>>>(W_ih, W_hh, b_ih, b_hh, x, rb, t_next);
        k_lstm<1><<<g, 256>>>(W_ih + (size_t)1 * WSTRIDE, W_hh + (size_t)1 * WSTRIDE,
                              b_ih + (size_t)1 * BSTRIDE, b_hh + (size_t)1 * BSTRIDE,
                              x, rb, t_next);
        k_lstm<2><<<g, 256>>>(W_ih + (size_t)2 * WSTRIDE, W_hh + (size_t)2 * WSTRIDE,
                              b_ih + (size_t)2 * BSTRIDE, b_hh + (size_t)2 * BSTRIDE,
                              x, rb, t_next);
    }
    k_out<<<(out_size + 255) / 256, 256>>>((float*)d_out, out_size);
}

// round 13
// speedup vs baseline: 1.3284x; 1.3284x over previous
#include <cuda_runtime.h>
#include <math.h>

#define T_STEPS 64
#define B_ 128
#define H_ 256
#define C_ 256
#define K_ 8
#define L_ 3
#define BK 1024
#define NEGV (-1e30f)

// ------------------------- device scratch (static, no allocs) ---------------
__device__ float g_WpT[H_ * C_];            // Wp transposed: [i][c]
__device__ float g_P0[C_ * 4 * H_];         // emb @ W_ih0^T + b_ih0 + b_hh0
__device__ float g_state[BK * H_];          // [B*K, H]
__device__ float g_h[2][L_][BK * H_];       // ping-pong hidden
__device__ float g_c[2][L_][BK * H_];       // ping-pong cell
__device__ float g_prefix[B_ * K_];
__device__ int   g_choices[B_ * K_ * T_STEPS];
__device__ int   g_src[BK];                 // gather source row (b*K + prev)
__device__ int   g_cls[BK];                 // chosen class per new beam row

// ------------------------- f32x2 packed helpers (sm_103a FFMA2) -------------
typedef unsigned long long u64;

__device__ __forceinline__ u64 fma2(u64 a, u64 b, u64 c) {
    u64 d;
    asm("fma.rn.f32x2 %0, %1, %2, %3;" : "=l"(d) : "l"(a), "l"(b), "l"(c));
    return d;
}
__device__ __forceinline__ u64 bcast2(float x) {
    u64 d; unsigned xi = __float_as_uint(x);
    asm("mov.b64 %0, {%1, %1};" : "=l"(d) : "r"(xi));
    return d;
}
__device__ __forceinline__ float lo2(u64 v) { return __uint_as_float((unsigned)v); }
__device__ __forceinline__ float hi2(u64 v) { return __uint_as_float((unsigned)(v >> 32)); }

// ------------------------- precise, fast-math-immune transcendentals --------
__device__ __forceinline__ float f_exp(float x) {
    const float LOG2E  = 1.4426950408889634f;
    const float LN2_HI = 0.693145751953125f;
    const float LN2_LO = 1.4286067653e-06f;
    float n = rintf(x * LOG2E);
    float r = fmaf(-n, LN2_HI, x);
    r = fmaf(-n, LN2_LO, r);
    float p = 1.9841269841e-4f;
    p = fmaf(p, r, 1.3888888889e-3f);
    p = fmaf(p, r, 8.3333333333e-3f);
    p = fmaf(p, r, 4.1666666667e-2f);
    p = fmaf(p, r, 1.6666666667e-1f);
    p = fmaf(p, r, 0.5f);
    p = fmaf(p, r, 1.0f);
    p = fmaf(p, r, 1.0f);
    int ni = (int)n;
    if (ni < -250) return 0.0f;
    if (ni >  250) ni = 250;
    int e1 = ni >> 1;
    int e2 = ni - e1;
    float s1 = __int_as_float((e1 + 127) << 23);
    float s2 = __int_as_float((e2 + 127) << 23);
    return p * s1 * s2;
}

__device__ __forceinline__ float f_tanh(float x) {
    float ax = fabsf(x);
    float t;
    if (ax < 0.25f) {
        float x2 = ax * ax;
        float p = 2.1869488536e-2f;
        p = fmaf(p, x2, -5.3968253968e-2f);
        p = fmaf(p, x2, 1.3333333333e-1f);
        p = fmaf(p, x2, -3.3333333333e-1f);
        t = fmaf(p * x2, ax, ax);
    } else {
        float e = f_exp(2.0f * ax);
        t = 1.0f - __fdiv_rn(2.0f, e + 1.0f);
    }
    return copysignf(t, x);
}

__device__ __forceinline__ float f_sig(float x) {
    return __fdiv_rn(1.0f, 1.0f + f_exp(-x));
}

// ------------------------- fused init: transpose + misc + P0 ----------------
__global__ __launch_bounds__(256) void k_init_combo(const float* __restrict__ x,
                                                    const float* __restrict__ Wp,
                                                    const float* __restrict__ emb,
                                                    const float* __restrict__ Wih0,
                                                    const float* __restrict__ bih0,
                                                    const float* __restrict__ bhh0) {
    int blk = blockIdx.x;
    if (blk < 1024) {
        int idx = blk * 256 + threadIdx.x;   // BK*H_ total
        int row = idx >> 8;
        int j = idx & 255;
        int b = row >> 3;
        g_state[idx] = x[b * H_ + j];
        if (idx < B_ * K_) g_prefix[idx] = ((idx & 7) == 0) ? 0.f : NEGV;
        if (idx < B_ * K_ * T_STEPS) g_choices[idx] = 0;
        return;
    }
    if (blk < 1280) {
        int idx = (blk - 1024) * 256 + threadIdx.x;   // H_*C_ total
        int i = idx >> 8, c = idx & 255;
        g_WpT[i * C_ + c] = Wp[c * H_ + i];
        return;
    }
    __shared__ float se[H_];
    int cidx = blk - 1280;
    se[threadIdx.x] = emb[cidx * H_ + threadIdx.x];
    __syncthreads();
    int t = threadIdx.x;
#pragma unroll
    for (int q = 0; q < 4; q++) {
        int n = q * H_ + t;
        const float4* wr = (const float4*)(Wih0 + (size_t)n * H_);
        float acc = 0.f;
#pragma unroll 8
        for (int k4 = 0; k4 < H_ / 4; k4++) {
            float4 w = wr[k4];
            float4 e = *(const float4*)&se[k4 * 4];
            acc += w.x * e.x + w.y * e.y + w.z * e.z + w.w * e.w;
        }
        g_P0[(size_t)cidx * (4 * H_) + n] = acc + bih0[n] + bhh0[n];
    }
}

// ------------------------- init LSTM, all 3 layers in one kernel ------------
__global__ __launch_bounds__(256) void k_init_lstm_all(const float* __restrict__ x,
                                                       const float* __restrict__ W_ih,
                                                       const float* __restrict__ b_ih,
                                                       const float* __restrict__ b_hh) {
    __shared__ float si[H_];
    int b = blockIdx.x;
    int t = threadIdx.x;
    const int WSTR = 4 * H_ * H_;
    const int BSTR = 4 * H_;
    for (int layer = 0; layer < L_; layer++) {
        const float* Wih = W_ih + (size_t)layer * WSTR;
        const float* bih = b_ih + (size_t)layer * BSTR;
        const float* bhh = b_hh + (size_t)layer * BSTR;
        const float* in = (layer == 0) ? (x + (size_t)b * H_)
                                       : (&g_h[0][layer - 1][0] + (size_t)(b * K_) * H_);
        si[t] = in[t];
        __syncthreads();
        float g4[4];
#pragma unroll
        for (int q = 0; q < 4; q++) {
            int n = q * H_ + t;
            const float4* wr = (const float4*)(Wih + (size_t)n * H_);
            float acc = 0.f;
#pragma unroll 8
            for (int k4 = 0; k4 < H_ / 4; k4++) {
                float4 w = wr[k4];
                float4 e = *(const float4*)&si[k4 * 4];
                acc += w.x * e.x + w.y * e.y + w.z * e.z + w.w * e.w;
            }
            g4[q] = acc + bih[n] + bhh[n];
        }
        float cn = f_sig(g4[0]) * f_tanh(g4[2]);
        float hn = f_sig(g4[3]) * f_tanh(cn);
#pragma unroll
        for (int kb = 0; kb < K_; kb++) {
            g_h[0][layer][((size_t)b * K_ + kb) * H_ + t] = hn;
            g_c[0][layer][((size_t)b * K_ + kb) * H_ + t] = cn;
        }
        __syncthreads();
    }
}

// ------------------------- projection + log_softmax + top-K -----------------
__global__ __launch_bounds__(256) void k_proj(const float* __restrict__ bp, int t) {
    __shared__ __align__(16) float s_state[K_][H_];
    __shared__ float s_pref[K_];
    __shared__ float s_red[8][K_];
    __shared__ float s_max[K_];
    __shared__ float s_lsum[K_];
    __shared__ float s_redv[8];
    __shared__ int   s_redi[8];
    __shared__ float s_topv[K_];
    __shared__ int   s_topi[K_];
    __shared__ int   s_prev[K_];
    __shared__ int   s_clss[K_];
    __shared__ int   s_ch[K_ * T_STEPS];

    int b = blockIdx.x;
    int tid = threadIdx.x;
    int warp = tid >> 5, lane = tid & 31;

    for (int u = tid; u < K_ * H_; u += 256)
        ((float*)s_state)[u] = g_state[(size_t)b * K_ * H_ + u];
    if (tid < K_) s_pref[tid] = g_prefix[b * K_ + tid];
    __syncthreads();

    int c = tid;
    float acc[K_];
#pragma unroll
    for (int k = 0; k < K_; k++) acc[k] = 0.f;
    for (int i0 = 0; i0 < H_; i0 += 4) {
        float4 sv[K_];
#pragma unroll
        for (int k = 0; k < K_; k++) sv[k] = *(const float4*)&s_state[k][i0];
        float w0 = g_WpT[(i0 + 0) * C_ + c];
        float w1 = g_WpT[(i0 + 1) * C_ + c];
        float w2 = g_WpT[(i0 + 2) * C_ + c];
        float w3 = g_WpT[(i0 + 3) * C_ + c];
#pragma unroll
        for (int k = 0; k < K_; k++) acc[k] += sv[k].x * w0;
#pragma unroll
        for (int k = 0; k < K_; k++) acc[k] += sv[k].y * w1;
#pragma unroll
        for (int k = 0; k < K_; k++) acc[k] += sv[k].z * w2;
#pragma unroll
        for (int k = 0; k < K_; k++) acc[k] += sv[k].w * w3;
    }
    float bb = bp[c];
#pragma unroll
    for (int k = 0; k < K_; k++) acc[k] += bb;

    // per-beam max
    {
        float m[K_];
#pragma unroll
        for (int k = 0; k < K_; k++) {
            float v = acc[k];
            for (int o = 16; o; o >>= 1) v = fmaxf(v, __shfl_xor_sync(0xffffffffu, v, o));
            m[k] = v;
        }
        if (lane == 0)
#pragma unroll
            for (int k = 0; k < K_; k++) s_red[warp][k] = m[k];
        __syncthreads();
        if (tid < K_) {
            float v = s_red[0][tid];
            for (int w2 = 1; w2 < 8; w2++) v = fmaxf(v, s_red[w2][tid]);
            s_max[tid] = v;
        }
        __syncthreads();
    }
    float mx[K_];
#pragma unroll
    for (int k = 0; k < K_; k++) mx[k] = s_max[k];
    // per-beam sum of exp (precise exp)
    {
        float s[K_];
#pragma unroll
        for (int k = 0; k < K_; k++) {
            float v = f_exp(acc[k] - mx[k]);
            for (int o = 16; o; o >>= 1) v += __shfl_xor_sync(0xffffffffu, v, o);
            s[k] = v;
        }
        __syncthreads();
        if (lane == 0)
#pragma unroll
            for (int k = 0; k < K_; k++) s_red[warp][k] = s[k];
        __syncthreads();
        if (tid < K_) {
            float v = 0.f;
            for (int w2 = 0; w2 < 8; w2++) v += s_red[w2][tid];
            s_lsum[tid] = (float)log((double)v);   // precise log
        }
        __syncthreads();
    }
    float jt[K_];
#pragma unroll
    for (int k = 0; k < K_; k++) jt[k] = s_pref[k] + ((acc[k] - mx[k]) - s_lsum[k]);

    // iterated block argmax (ties -> lowest flat idx, matching jax top_k)
    for (int it = 0; it < K_; it++) {
        float bv = -INFINITY;
        int bi = 0x7fffffff;
#pragma unroll
        for (int k = 0; k < K_; k++) {
            if (jt[k] > bv) { bv = jt[k]; bi = k * C_ + c; }
        }
        for (int o = 16; o; o >>= 1) {
            float ov = __shfl_xor_sync(0xffffffffu, bv, o);
            int   oi = __shfl_xor_sync(0xffffffffu, bi, o);
            if (ov > bv || (ov == bv && oi < bi)) { bv = ov; bi = oi; }
        }
        if (lane == 0) { s_redv[warp] = bv; s_redi[warp] = bi; }
        __syncthreads();
        if (tid == 0) {
            float fv = s_redv[0]; int fi = s_redi[0];
            for (int w2 = 1; w2 < 8; w2++)
                if (s_redv[w2] > fv || (s_redv[w2] == fv && s_redi[w2] < fi)) {
                    fv = s_redv[w2]; fi = s_redi[w2];
                }
            s_topv[it] = fv; s_topi[it] = fi;
        }
        __syncthreads();
        int sel = s_topi[it];
        if ((sel & (C_ - 1)) == c) jt[sel >> 8] = -INFINITY;
    }

    if (tid < K_) {
        int sel = s_topi[tid];
        int prev = sel >> 8;
        int cls = sel & (C_ - 1);
        g_prefix[b * K_ + tid] = s_topv[tid];
        g_src[b * K_ + tid] = b * K_ + prev;
        g_cls[b * K_ + tid] = cls;
        s_prev[tid] = prev;
        s_clss[tid] = cls;
    }
    __syncthreads();
    for (int u = tid; u < K_ * T_STEPS; u += 256) {
        int kq = u >> 6, tt = u & 63;
        s_ch[u] = g_choices[(b * K_ + s_prev[kq]) * T_STEPS + tt];
    }
    __syncthreads();
    for (int u = tid; u < K_ * T_STEPS; u += 256) {
        int kq = u >> 6, tt = u & 63;
        g_choices[(b * K_ + kq) * T_STEPS + tt] = (tt == t) ? s_clss[kq] : s_ch[u];
    }
}

// ------------------------- LSTM layer GEMM + gates --------------------------
// Tile: 64 rows x 64 gate-cols (16 j x 4 gates), grid 16x16 = 256 blocks,
// 256 threads -> 2 CTAs per SM (barrier-decoupled: one block's __syncthreads
// convoy overlaps the other block's compute). Per thread: 4 rows x 4 gates.
// Per-output FMA chain (k ascending, fma2 pairing (g0,g1)/(g2,g3)) identical
// to rounds 6-10 -> bit-exact; only the block partitioning changed.
template <int LAYER>
__global__ __launch_bounds__(256) void k_lstm(const float* __restrict__ Wih,
                                              const float* __restrict__ Whh,
                                              const float* __restrict__ bih,
                                              const float* __restrict__ bhh,
                                              const float* __restrict__ x,
                                              int rb, int t_next) {
    __shared__ __align__(16) float As[2][16][64];
    __shared__ __align__(16) float Ws[2][16][64];
    __shared__ int s_src[64];
    __shared__ int s_cls[64];

    const float* hcur = g_h[rb][LAYER];
    const float* ccur = g_c[rb][LAYER];
    float* hnxt = g_h[1 - rb][LAYER];
    float* cnxt = g_c[1 - rb][LAYER];
    const float* inp = (LAYER == 0) ? (const float*)0 : g_h[1 - rb][LAYER - 1];

    int tid = threadIdx.x;
    int rBase = blockIdx.x * 64;
    int jBase = blockIdx.y * 16;

    if (tid < 64) {
        s_src[tid] = g_src[rBase + tid];
        if (LAYER == 0) s_cls[tid] = g_cls[rBase + tid];
    }
    __syncthreads();

    // ---- staging indices: one float4 per thread for A and for W ----
    int arow = tid >> 2;            // 0..63: local A row (4 threads/row)
    int akq  = (tid & 3) * 4;       // k offset within 16-tile (0,4,8,12)
    int wrow = tid >> 2;            // 0..63: local W col (n_l = j_local*4+gate)
    int wkq  = (tid & 3) * 4;       // k offset (0,4,8,12)

    const float* aHid = hcur + (size_t)s_src[arow] * H_;
    const float* aIn  = (LAYER == 0) ? (const float*)0
                                     : inp + (size_t)(rBase + arow) * H_;
    const size_t wgrow = (size_t)((wrow & 3) * H_ + jBase + (wrow >> 2)) * H_;
    const float* wiP = Wih + wgrow;
    const float* whP = Whh + wgrow;

    const int KSTART = (LAYER == 0) ? 256 : 0;
    const int NT = (512 - KSTART) / 16;

    int tx = tid & 15, ty = tid >> 4;   // tx: j, ty 0..15: 4-row group

    u64 acc[4][2];
#pragma unroll
    for (int r = 0; r < 4; r++) { acc[r][0] = 0ull; acc[r][1] = 0ull; }

    // ---- prologue: load tile 0 ----
    float4 a0, w0;
    {
        int k = KSTART + akq;
        const float* p = (LAYER > 0 && k < 256) ? (aIn + k) : (aHid + (k - 256));
        a0 = *(const float4*)p;
        int kw = KSTART + wkq;
        const float* q = (LAYER > 0 && kw < 256) ? (wiP + kw) : (whP + (kw - 256));
        w0 = *(const float4*)q;
    }
    {
        As[0][akq + 0][arow] = a0.x; As[0][akq + 1][arow] = a0.y;
        As[0][akq + 2][arow] = a0.z; As[0][akq + 3][arow] = a0.w;
        Ws[0][wkq + 0][wrow] = w0.x; Ws[0][wkq + 1][wrow] = w0.y;
        Ws[0][wkq + 2][wrow] = w0.z; Ws[0][wkq + 3][wrow] = w0.w;
    }
    __syncthreads();

    for (int kt = 0; kt < NT; kt++) {
        int buf = kt & 1;
        bool more = (kt + 1 < NT);
        if (more) {
            int k = KSTART + (kt + 1) * 16 + akq;
            const float* p = (LAYER > 0 && k < 256) ? (aIn + k) : (aHid + (k - 256));
            a0 = *(const float4*)p;
            int kw = KSTART + (kt + 1) * 16 + wkq;
            const float* q = (LAYER > 0 && kw < 256) ? (wiP + kw) : (whP + (kw - 256));
            w0 = *(const float4*)q;
        }
#pragma unroll
        for (int kk = 0; kk < 16; kk++) {
            float4 av = *(const float4*)&As[buf][kk][ty * 4];
            ulonglong2 wv = *(const ulonglong2*)&Ws[buf][kk][tx * 4];
            u64 bb;
            bb = bcast2(av.x); acc[0][0] = fma2(bb, wv.x, acc[0][0]); acc[0][1] = fma2(bb, wv.y, acc[0][1]);
            bb = bcast2(av.y); acc[1][0] = fma2(bb, wv.x, acc[1][0]); acc[1][1] = fma2(bb, wv.y, acc[1][1]);
            bb = bcast2(av.z); acc[2][0] = fma2(bb, wv.x, acc[2][0]); acc[2][1] = fma2(bb, wv.y, acc[2][1]);
            bb = bcast2(av.w); acc[3][0] = fma2(bb, wv.x, acc[3][0]); acc[3][1] = fma2(bb, wv.y, acc[3][1]);
        }
        if (more) {
            int nb = buf ^ 1;
            As[nb][akq + 0][arow] = a0.x; As[nb][akq + 1][arow] = a0.y;
            As[nb][akq + 2][arow] = a0.z; As[nb][akq + 3][arow] = a0.w;
            Ws[nb][wkq + 0][wrow] = w0.x; Ws[nb][wkq + 1][wrow] = w0.y;
            Ws[nb][wkq + 2][wrow] = w0.z; Ws[nb][wkq + 3][wrow] = w0.w;
        }
        __syncthreads();
    }

    // ---- epilogue (expressions identical to rounds 6-10) ----
    int j = jBase + tx;
    float bias[4];
    if (LAYER > 0) {
#pragma unroll
        for (int q = 0; q < 4; q++) bias[q] = bih[q * H_ + j] + bhh[q * H_ + j];
    }
#pragma unroll
    for (int r = 0; r < 4; r++) {
        int rl = ty * 4 + r;
        int row_g = rBase + rl;
        int b = row_g >> 3;
        float gi = lo2(acc[r][0]), gf = hi2(acc[r][0]);
        float gg = lo2(acc[r][1]), go = hi2(acc[r][1]);
        if (LAYER == 0) {
            const float* p0 = g_P0 + (size_t)s_cls[rl] * (4 * H_);
            gi += p0[0 * H_ + j]; gf += p0[1 * H_ + j];
            gg += p0[2 * H_ + j]; go += p0[3 * H_ + j];
        } else {
            gi += bias[0]; gf += bias[1]; gg += bias[2]; go += bias[3];
        }
        float cold = ccur[(size_t)s_src[rl] * H_ + j];
        float cn = f_sig(gf) * cold + f_sig(gi) * f_tanh(gg);
        float hn = f_sig(go) * f_tanh(cn);
        cnxt[(size_t)row_g * H_ + j] = cn;
        hnxt[(size_t)row_g * H_ + j] = hn;
        if (LAYER == 2)
            g_state[(size_t)row_g * H_ + j] = hn + x[(size_t)t_next * B_ * H_ + b * H_ + j];
    }
}

// ------------------------- output ------------------------------------------
__global__ void k_out(float* __restrict__ out, int n) {
    int i = blockIdx.x * 256 + threadIdx.x;
    if (i >= n) return;
    if (i < B_ * K_ * T_STEPS) out[i] = (float)g_choices[i];
    else if (i < B_ * K_ * T_STEPS + B_ * K_) out[i] = g_prefix[i - B_ * K_ * T_STEPS];
    else out[i] = 0.f;
}

// ------------------------- host --------------------------------------------
extern "C" void kernel_launch(void* const* d_in, const int* in_sizes, int n_in,
                              void* d_out, int out_size) {
    const float* x    = (const float*)d_in[0];
    const float* emb  = (const float*)d_in[1];
    const float* W_ih = (const float*)d_in[2];
    const float* W_hh = (const float*)d_in[3];
    const float* b_ih = (const float*)d_in[4];
    const float* b_hh = (const float*)d_in[5];
    const float* Wp   = (const float*)d_in[6];
    const float* bp   = (const float*)d_in[7];

    const int WSTRIDE = 4 * H_ * H_;
    const int BSTRIDE = 4 * H_;

    k_init_combo<<<1536, 256>>>(x, Wp, emb, W_ih, b_ih, b_hh);
    k_init_lstm_all<<<B_, 256>>>(x, W_ih, b_ih, b_hh);

    dim3 g(16, 16);
    for (int t = 0; t < T_STEPS; t++) {
        int rb = t & 1;
        int t_next = (t + 1 < T_STEPS) ? (t + 1) : (T_STEPS - 1);
        k_proj<<<B_, 256>>>(bp, t);
        k_lstm<0><<<g, 256>>>(W_ih, W_hh, b_ih, b_hh, x, rb, t_next);
        k_lstm<1><<<g, 256>>>(W_ih + (size_t)1 * WSTRIDE, W_hh + (size_t)1 * WSTRIDE,
                              b_ih + (size_t)1 * BSTRIDE, b_hh + (size_t)1 * BSTRIDE,
                              x, rb, t_next);
        k_lstm<2><<<g, 256>>>(W_ih + (size_t)2 * WSTRIDE, W_hh + (size_t)2 * WSTRIDE,
                              b_ih + (size_t)2 * BSTRIDE, b_hh + (size_t)2 * BSTRIDE,
                              x, rb, t_next);
    }
    k_out<<<(out_size + 255) / 256, 256>>>((float*)d_out, out_size);
}

// round 14
// speedup vs baseline: 1.3713x; 1.0323x over previous
#include <cuda_runtime.h>
#include <math.h>

#define T_STEPS 64
#define B_ 128
#define H_ 256
#define C_ 256
#define K_ 8
#define L_ 3
#define BK 1024
#define NEGV (-1e30f)

// ------------------------- device scratch (static, no allocs) ---------------
__device__ float g_WpT[H_ * C_];            // Wp transposed: [i][c]
__device__ float g_P0[C_ * 4 * H_];         // emb @ W_ih0^T + b_ih0 + b_hh0
__device__ float g_state[BK * H_];          // [B*K, H]
__device__ float g_h[2][L_][BK * H_];       // ping-pong hidden
__device__ float g_c[2][L_][BK * H_];       // ping-pong cell
__device__ float g_prefix[B_ * K_];
__device__ int   g_choices[B_ * K_ * T_STEPS];
__device__ int   g_src[BK];                 // gather source row (b*K + prev)
__device__ int   g_cls[BK];                 // chosen class per new beam row

// ------------------------- PDL primitives (sm_90+) --------------------------
__device__ __forceinline__ void pdl_wait() {
    asm volatile("griddepcontrol.wait;" ::: "memory");
}
__device__ __forceinline__ void pdl_trigger() {
    __threadfence();
    asm volatile("griddepcontrol.launch_dependents;" ::: "memory");
}

// ------------------------- f32x2 packed helpers (sm_103a FFMA2) -------------
typedef unsigned long long u64;

__device__ __forceinline__ u64 fma2(u64 a, u64 b, u64 c) {
    u64 d;
    asm("fma.rn.f32x2 %0, %1, %2, %3;" : "=l"(d) : "l"(a), "l"(b), "l"(c));
    return d;
}
__device__ __forceinline__ u64 bcast2(float x) {
    u64 d; unsigned xi = __float_as_uint(x);
    asm("mov.b64 %0, {%1, %1};" : "=l"(d) : "r"(xi));
    return d;
}
__device__ __forceinline__ float lo2(u64 v) { return __uint_as_float((unsigned)v); }
__device__ __forceinline__ float hi2(u64 v) { return __uint_as_float((unsigned)(v >> 32)); }

// ------------------------- precise, fast-math-immune transcendentals --------
__device__ __forceinline__ float f_exp(float x) {
    const float LOG2E  = 1.4426950408889634f;
    const float LN2_HI = 0.693145751953125f;
    const float LN2_LO = 1.4286067653e-06f;
    float n = rintf(x * LOG2E);
    float r = fmaf(-n, LN2_HI, x);
    r = fmaf(-n, LN2_LO, r);
    float p = 1.9841269841e-4f;
    p = fmaf(p, r, 1.3888888889e-3f);
    p = fmaf(p, r, 8.3333333333e-3f);
    p = fmaf(p, r, 4.1666666667e-2f);
    p = fmaf(p, r, 1.6666666667e-1f);
    p = fmaf(p, r, 0.5f);
    p = fmaf(p, r, 1.0f);
    p = fmaf(p, r, 1.0f);
    int ni = (int)n;
    if (ni < -250) return 0.0f;
    if (ni >  250) ni = 250;
    int e1 = ni >> 1;
    int e2 = ni - e1;
    float s1 = __int_as_float((e1 + 127) << 23);
    float s2 = __int_as_float((e2 + 127) << 23);
    return p * s1 * s2;
}

__device__ __forceinline__ float f_tanh(float x) {
    float ax = fabsf(x);
    float t;
    if (ax < 0.25f) {
        float x2 = ax * ax;
        float p = 2.1869488536e-2f;
        p = fmaf(p, x2, -5.3968253968e-2f);
        p = fmaf(p, x2, 1.3333333333e-1f);
        p = fmaf(p, x2, -3.3333333333e-1f);
        t = fmaf(p * x2, ax, ax);
    } else {
        float e = f_exp(2.0f * ax);
        t = 1.0f - __fdiv_rn(2.0f, e + 1.0f);
    }
    return copysignf(t, x);
}

__device__ __forceinline__ float f_sig(float x) {
    return __fdiv_rn(1.0f, 1.0f + f_exp(-x));
}

// ------------------------- fused init: transpose + misc + P0 ----------------
__global__ __launch_bounds__(256) void k_init_combo(const float* __restrict__ x,
                                                    const float* __restrict__ Wp,
                                                    const float* __restrict__ emb,
                                                    const float* __restrict__ Wih0,
                                                    const float* __restrict__ bih0,
                                                    const float* __restrict__ bhh0) {
    int blk = blockIdx.x;
    if (blk < 1024) {
        int idx = blk * 256 + threadIdx.x;   // BK*H_ total
        int row = idx >> 8;
        int j = idx & 255;
        int b = row >> 3;
        g_state[idx] = x[b * H_ + j];
        if (idx < B_ * K_) g_prefix[idx] = ((idx & 7) == 0) ? 0.f : NEGV;
        if (idx < B_ * K_ * T_STEPS) g_choices[idx] = 0;
        return;
    }
    if (blk < 1280) {
        int idx = (blk - 1024) * 256 + threadIdx.x;   // H_*C_ total
        int i = idx >> 8, c = idx & 255;
        g_WpT[i * C_ + c] = Wp[c * H_ + i];
        return;
    }
    __shared__ float se[H_];
    int cidx = blk - 1280;
    se[threadIdx.x] = emb[cidx * H_ + threadIdx.x];
    __syncthreads();
    int t = threadIdx.x;
#pragma unroll
    for (int q = 0; q < 4; q++) {
        int n = q * H_ + t;
        const float4* wr = (const float4*)(Wih0 + (size_t)n * H_);
        float acc = 0.f;
#pragma unroll 8
        for (int k4 = 0; k4 < H_ / 4; k4++) {
            float4 w = wr[k4];
            float4 e = *(const float4*)&se[k4 * 4];
            acc += w.x * e.x + w.y * e.y + w.z * e.z + w.w * e.w;
        }
        g_P0[(size_t)cidx * (4 * H_) + n] = acc + bih0[n] + bhh0[n];
    }
}

// ------------------------- init LSTM, all 3 layers in one kernel ------------
__global__ __launch_bounds__(256) void k_init_lstm_all(const float* __restrict__ x,
                                                       const float* __restrict__ W_ih,
                                                       const float* __restrict__ b_ih,
                                                       const float* __restrict__ b_hh) {
    __shared__ float si[H_];
    int b = blockIdx.x;
    int t = threadIdx.x;
    const int WSTR = 4 * H_ * H_;
    const int BSTR = 4 * H_;
    for (int layer = 0; layer < L_; layer++) {
        const float* Wih = W_ih + (size_t)layer * WSTR;
        const float* bih = b_ih + (size_t)layer * BSTR;
        const float* bhh = b_hh + (size_t)layer * BSTR;
        const float* in = (layer == 0) ? (x + (size_t)b * H_)
                                       : (&g_h[0][layer - 1][0] + (size_t)(b * K_) * H_);
        si[t] = in[t];
        __syncthreads();
        float g4[4];
#pragma unroll
        for (int q = 0; q < 4; q++) {
            int n = q * H_ + t;
            const float4* wr = (const float4*)(Wih + (size_t)n * H_);
            float acc = 0.f;
#pragma unroll 8
            for (int k4 = 0; k4 < H_ / 4; k4++) {
                float4 w = wr[k4];
                float4 e = *(const float4*)&si[k4 * 4];
                acc += w.x * e.x + w.y * e.y + w.z * e.z + w.w * e.w;
            }
            g4[q] = acc + bih[n] + bhh[n];
        }
        float cn = f_sig(g4[0]) * f_tanh(g4[2]);
        float hn = f_sig(g4[3]) * f_tanh(cn);
#pragma unroll
        for (int kb = 0; kb < K_; kb++) {
            g_h[0][layer][((size_t)b * K_ + kb) * H_ + t] = hn;
            g_c[0][layer][((size_t)b * K_ + kb) * H_ + t] = cn;
        }
        __syncthreads();
    }
    pdl_trigger();
}

// ------------------------- projection + log_softmax + top-K -----------------
__global__ __launch_bounds__(256) void k_proj(const float* __restrict__ bp, int t) {
    __shared__ __align__(16) float s_state[K_][H_];
    __shared__ float s_pref[K_];
    __shared__ float s_red[8][K_];
    __shared__ float s_max[K_];
    __shared__ float s_lsum[K_];
    __shared__ float s_redv[8];
    __shared__ int   s_redi[8];
    __shared__ float s_topv[K_];
    __shared__ int   s_topi[K_];
    __shared__ int   s_prev[K_];
    __shared__ int   s_clss[K_];
    __shared__ int   s_ch[K_ * T_STEPS];

    int b = blockIdx.x;
    int tid = threadIdx.x;
    int warp = tid >> 5, lane = tid & 31;

    pdl_wait();

    for (int u = tid; u < K_ * H_; u += 256)
        ((float*)s_state)[u] = g_state[(size_t)b * K_ * H_ + u];
    if (tid < K_) s_pref[tid] = g_prefix[b * K_ + tid];
    __syncthreads();

    int c = tid;
    float acc[K_];
#pragma unroll
    for (int k = 0; k < K_; k++) acc[k] = 0.f;
    for (int i0 = 0; i0 < H_; i0 += 4) {
        float4 sv[K_];
#pragma unroll
        for (int k = 0; k < K_; k++) sv[k] = *(const float4*)&s_state[k][i0];
        float w0 = g_WpT[(i0 + 0) * C_ + c];
        float w1 = g_WpT[(i0 + 1) * C_ + c];
        float w2 = g_WpT[(i0 + 2) * C_ + c];
        float w3 = g_WpT[(i0 + 3) * C_ + c];
#pragma unroll
        for (int k = 0; k < K_; k++) acc[k] += sv[k].x * w0;
#pragma unroll
        for (int k = 0; k < K_; k++) acc[k] += sv[k].y * w1;
#pragma unroll
        for (int k = 0; k < K_; k++) acc[k] += sv[k].z * w2;
#pragma unroll
        for (int k = 0; k < K_; k++) acc[k] += sv[k].w * w3;
    }
    float bb = bp[c];
#pragma unroll
    for (int k = 0; k < K_; k++) acc[k] += bb;

    // per-beam max
    {
        float m[K_];
#pragma unroll
        for (int k = 0; k < K_; k++) {
            float v = acc[k];
            for (int o = 16; o; o >>= 1) v = fmaxf(v, __shfl_xor_sync(0xffffffffu, v, o));
            m[k] = v;
        }
        if (lane == 0)
#pragma unroll
            for (int k = 0; k < K_; k++) s_red[warp][k] = m[k];
        __syncthreads();
        if (tid < K_) {
            float v = s_red[0][tid];
            for (int w2 = 1; w2 < 8; w2++) v = fmaxf(v, s_red[w2][tid]);
            s_max[tid] = v;
        }
        __syncthreads();
    }
    float mx[K_];
#pragma unroll
    for (int k = 0; k < K_; k++) mx[k] = s_max[k];
    // per-beam sum of exp (precise exp)
    {
        float s[K_];
#pragma unroll
        for (int k = 0; k < K_; k++) {
            float v = f_exp(acc[k] - mx[k]);
            for (int o = 16; o; o >>= 1) v += __shfl_xor_sync(0xffffffffu, v, o);
            s[k] = v;
        }
        __syncthreads();
        if (lane == 0)
#pragma unroll
            for (int k = 0; k < K_; k++) s_red[warp][k] = s[k];
        __syncthreads();
        if (tid < K_) {
            float v = 0.f;
            for (int w2 = 0; w2 < 8; w2++) v += s_red[w2][tid];
            s_lsum[tid] = (float)log((double)v);   // precise log
        }
        __syncthreads();
    }
    float jt[K_];
#pragma unroll
    for (int k = 0; k < K_; k++) jt[k] = s_pref[k] + ((acc[k] - mx[k]) - s_lsum[k]);

    // iterated block argmax (ties -> lowest flat idx, matching jax top_k)
    for (int it = 0; it < K_; it++) {
        float bv = -INFINITY;
        int bi = 0x7fffffff;
#pragma unroll
        for (int k = 0; k < K_; k++) {
            if (jt[k] > bv) { bv = jt[k]; bi = k * C_ + c; }
        }
        for (int o = 16; o; o >>= 1) {
            float ov = __shfl_xor_sync(0xffffffffu, bv, o);
            int   oi = __shfl_xor_sync(0xffffffffu, bi, o);
            if (ov > bv || (ov == bv && oi < bi)) { bv = ov; bi = oi; }
        }
        if (lane == 0) { s_redv[warp] = bv; s_redi[warp] = bi; }
        __syncthreads();
        if (tid == 0) {
            float fv = s_redv[0]; int fi = s_redi[0];
            for (int w2 = 1; w2 < 8; w2++)
                if (s_redv[w2] > fv || (s_redv[w2] == fv && s_redi[w2] < fi)) {
                    fv = s_redv[w2]; fi = s_redi[w2];
                }
            s_topv[it] = fv; s_topi[it] = fi;
        }
        __syncthreads();
        int sel = s_topi[it];
        if ((sel & (C_ - 1)) == c) jt[sel >> 8] = -INFINITY;
    }

    if (tid < K_) {
        int sel = s_topi[tid];
        int prev = sel >> 8;
        int cls = sel & (C_ - 1);
        g_prefix[b * K_ + tid] = s_topv[tid];
        g_src[b * K_ + tid] = b * K_ + prev;
        g_cls[b * K_ + tid] = cls;
        s_prev[tid] = prev;
        s_clss[tid] = cls;
    }
    __syncthreads();
    for (int u = tid; u < K_ * T_STEPS; u += 256) {
        int kq = u >> 6, tt = u & 63;
        s_ch[u] = g_choices[(b * K_ + s_prev[kq]) * T_STEPS + tt];
    }
    __syncthreads();
    for (int u = tid; u < K_ * T_STEPS; u += 256) {
        int kq = u >> 6, tt = u & 63;
        g_choices[(b * K_ + kq) * T_STEPS + tt] = (tt == t) ? s_clss[kq] : s_ch[u];
    }
    pdl_trigger();
}

// ------------------------- LSTM layer GEMM + gates (round-7 exact) ----------
template <int LAYER>
__global__ __launch_bounds__(256) void k_lstm(const float* __restrict__ Wih,
                                              const float* __restrict__ Whh,
                                              const float* __restrict__ bih,
                                              const float* __restrict__ bhh,
                                              const float* __restrict__ x,
                                              int rb, int t_next) {
    __shared__ __align__(16) float As[2][16][128];
    __shared__ __align__(16) float Ws[2][16][64];
    __shared__ int s_src[128];
    __shared__ int s_cls[128];

    const float* hcur = g_h[rb][LAYER];
    const float* ccur = g_c[rb][LAYER];
    float* hnxt = g_h[1 - rb][LAYER];
    float* cnxt = g_c[1 - rb][LAYER];
    const float* inp = (LAYER == 0) ? (const float*)0 : g_h[1 - rb][LAYER - 1];

    int tid = threadIdx.x;
    int rBase = blockIdx.x * 128;
    int jBase = blockIdx.y * 16;

    pdl_wait();

    if (tid < 128) {
        s_src[tid] = g_src[rBase + tid];
        if (LAYER == 0) s_cls[tid] = g_cls[rBase + tid];
    }
    __syncthreads();

    int arow = tid >> 1;            // 0..127: local A row
    int akq  = (tid & 1) * 8;       // k offset within 16-tile (0 or 8)
    int wrow = tid >> 2;            // 0..63: local W col (n_l = j_local*4+gate)
    int wkq  = (tid & 3) * 4;       // k offset (0,4,8,12)

    const float* aHid = hcur + (size_t)s_src[arow] * H_;
    const float* aIn  = (LAYER == 0) ? (const float*)0
                                     : inp + (size_t)(rBase + arow) * H_;
    const size_t wgrow = (size_t)((wrow & 3) * H_ + jBase + (wrow >> 2)) * H_;
    const float* wiP = Wih + wgrow;
    const float* whP = Whh + wgrow;

    const int KSTART = (LAYER == 0) ? 256 : 0;
    const int NT = (512 - KSTART) / 16;

    int tx = tid & 15, ty = tid >> 4;

    u64 acc[8][2];
#pragma unroll
    for (int r = 0; r < 8; r++) { acc[r][0] = 0ull; acc[r][1] = 0ull; }

    float4 a0, a1, w0;
    {
        int k = KSTART + akq;
        const float* p = (LAYER > 0 && k < 256) ? (aIn + k) : (aHid + (k - 256));
        a0 = *(const float4*)p; a1 = *(const float4*)(p + 4);
        int kw = KSTART + wkq;
        const float* q = (LAYER > 0 && kw < 256) ? (wiP + kw) : (whP + (kw - 256));
        w0 = *(const float4*)q;
    }
    {
        As[0][akq + 0][arow] = a0.x; As[0][akq + 1][arow] = a0.y;
        As[0][akq + 2][arow] = a0.z; As[0][akq + 3][arow] = a0.w;
        As[0][akq + 4][arow] = a1.x; As[0][akq + 5][arow] = a1.y;
        As[0][akq + 6][arow] = a1.z; As[0][akq + 7][arow] = a1.w;
        Ws[0][wkq + 0][wrow] = w0.x; Ws[0][wkq + 1][wrow] = w0.y;
        Ws[0][wkq + 2][wrow] = w0.z; Ws[0][wkq + 3][wrow] = w0.w;
    }
    __syncthreads();

    for (int kt = 0; kt < NT; kt++) {
        int buf = kt & 1;
        bool more = (kt + 1 < NT);
        if (more) {
            int k = KSTART + (kt + 1) * 16 + akq;
            const float* p = (LAYER > 0 && k < 256) ? (aIn + k) : (aHid + (k - 256));
            a0 = *(const float4*)p; a1 = *(const float4*)(p + 4);
            int kw = KSTART + (kt + 1) * 16 + wkq;
            const float* q = (LAYER > 0 && kw < 256) ? (wiP + kw) : (whP + (kw - 256));
            w0 = *(const float4*)q;
        }
#pragma unroll
        for (int kk = 0; kk < 16; kk++) {
            float4 av0 = *(const float4*)&As[buf][kk][ty * 8];
            float4 av1 = *(const float4*)&As[buf][kk][ty * 8 + 4];
            ulonglong2 wv = *(const ulonglong2*)&Ws[buf][kk][tx * 4];
            u64 bb;
            bb = bcast2(av0.x); acc[0][0] = fma2(bb, wv.x, acc[0][0]); acc[0][1] = fma2(bb, wv.y, acc[0][1]);
            bb = bcast2(av0.y); acc[1][0] = fma2(bb, wv.x, acc[1][0]); acc[1][1] = fma2(bb, wv.y, acc[1][1]);
            bb = bcast2(av0.z); acc[2][0] = fma2(bb, wv.x, acc[2][0]); acc[2][1] = fma2(bb, wv.y, acc[2][1]);
            bb = bcast2(av0.w); acc[3][0] = fma2(bb, wv.x, acc[3][0]); acc[3][1] = fma2(bb, wv.y, acc[3][1]);
            bb = bcast2(av1.x); acc[4][0] = fma2(bb, wv.x, acc[4][0]); acc[4][1] = fma2(bb, wv.y, acc[4][1]);
            bb = bcast2(av1.y); acc[5][0] = fma2(bb, wv.x, acc[5][0]); acc[5][1] = fma2(bb, wv.y, acc[5][1]);
            bb = bcast2(av1.z); acc[6][0] = fma2(bb, wv.x, acc[6][0]); acc[6][1] = fma2(bb, wv.y, acc[6][1]);
            bb = bcast2(av1.w); acc[7][0] = fma2(bb, wv.x, acc[7][0]); acc[7][1] = fma2(bb, wv.y, acc[7][1]);
        }
        if (more) {
            int nb = buf ^ 1;
            As[nb][akq + 0][arow] = a0.x; As[nb][akq + 1][arow] = a0.y;
            As[nb][akq + 2][arow] = a0.z; As[nb][akq + 3][arow] = a0.w;
            As[nb][akq + 4][arow] = a1.x; As[nb][akq + 5][arow] = a1.y;
            As[nb][akq + 6][arow] = a1.z; As[nb][akq + 7][arow] = a1.w;
            Ws[nb][wkq + 0][wrow] = w0.x; Ws[nb][wkq + 1][wrow] = w0.y;
            Ws[nb][wkq + 2][wrow] = w0.z; Ws[nb][wkq + 3][wrow] = w0.w;
        }
        __syncthreads();
    }

    int j = jBase + tx;
    float bias[4];
    if (LAYER > 0) {
#pragma unroll
        for (int q = 0; q < 4; q++) bias[q] = bih[q * H_ + j] + bhh[q * H_ + j];
    }
#pragma unroll
    for (int r = 0; r < 8; r++) {
        int rl = ty * 8 + r;
        int row_g = rBase + rl;
        int b = row_g >> 3;
        float gi = lo2(acc[r][0]), gf = hi2(acc[r][0]);
        float gg = lo2(acc[r][1]), go = hi2(acc[r][1]);
        if (LAYER == 0) {
            const float* p0 = g_P0 + (size_t)s_cls[rl] * (4 * H_);
            gi += p0[0 * H_ + j]; gf += p0[1 * H_ + j];
            gg += p0[2 * H_ + j]; go += p0[3 * H_ + j];
        } else {
            gi += bias[0]; gf += bias[1]; gg += bias[2]; go += bias[3];
        }
        float cold = ccur[(size_t)s_src[rl] * H_ + j];
        float cn = f_sig(gf) * cold + f_sig(gi) * f_tanh(gg);
        float hn = f_sig(go) * f_tanh(cn);
        cnxt[(size_t)row_g * H_ + j] = cn;
        hnxt[(size_t)row_g * H_ + j] = hn;
        if (LAYER == 2)
            g_state[(size_t)row_g * H_ + j] = hn + x[(size_t)t_next * B_ * H_ + b * H_ + j];
    }
    pdl_trigger();
}

// ------------------------- output ------------------------------------------
__global__ void k_out(float* __restrict__ out, int n) {
    pdl_wait();
    int i = blockIdx.x * 256 + threadIdx.x;
    if (i >= n) return;
    if (i < B_ * K_ * T_STEPS) out[i] = (float)g_choices[i];
    else if (i < B_ * K_ * T_STEPS + B_ * K_) out[i] = g_prefix[i - B_ * K_ * T_STEPS];
    else out[i] = 0.f;
}

// ------------------------- host: PDL launch helper --------------------------
static inline void launch_pdl(const void* func, dim3 grid, dim3 block, void** args) {
    cudaLaunchConfig_t cfg = {};
    cfg.gridDim = grid;
    cfg.blockDim = block;
    cfg.dynamicSmemBytes = 0;
    cfg.stream = 0;   // legacy default stream (same as <<<>>>, captured by harness)
    cudaLaunchAttribute attr[1];
    attr[0].id = cudaLaunchAttributeProgrammaticStreamSerialization;
    attr[0].val.programmaticStreamSerializationAllowed = 1;
    cfg.attrs = attr;
    cfg.numAttrs = 1;
    cudaLaunchKernelExC(&cfg, func, args);
}

// ------------------------- host --------------------------------------------
extern "C" void kernel_launch(void* const* d_in, const int* in_sizes, int n_in,
                              void* d_out, int out_size) {
    const float* x    = (const float*)d_in[0];
    const float* emb  = (const float*)d_in[1];
    const float* W_ih = (const float*)d_in[2];
    const float* W_hh = (const float*)d_in[3];
    const float* b_ih = (const float*)d_in[4];
    const float* b_hh = (const float*)d_in[5];
    const float* Wp   = (const float*)d_in[6];
    const float* bp   = (const float*)d_in[7];

    const size_t WSTRIDE = 4 * H_ * H_;
    const size_t BSTRIDE = 4 * H_;

    k_init_combo<<<1536, 256>>>(x, Wp, emb, W_ih, b_ih, b_hh);
    k_init_lstm_all<<<B_, 256>>>(x, W_ih, b_ih, b_hh);

    dim3 g(8, 16);
    dim3 b256(256);
    for (int t = 0; t < T_STEPS; t++) {
        int rb = t & 1;
        int t_next = (t + 1 < T_STEPS) ? (t + 1) : (T_STEPS - 1);

        {
            void* args[] = { (void*)&bp, (void*)&t };
            launch_pdl((const void*)k_proj, dim3(B_), b256, args);
        }
        {
            const float *wi = W_ih, *wh = W_hh, *bi = b_ih, *bh = b_hh;
            void* args[] = { (void*)&wi, (void*)&wh, (void*)&bi, (void*)&bh,
                             (void*)&x, (void*)&rb, (void*)&t_next };
            launch_pdl((const void*)k_lstm<0>, g, b256, args);
        }
        {
            const float *wi = W_ih + 1 * WSTRIDE, *wh = W_hh + 1 * WSTRIDE;
            const float *bi = b_ih + 1 * BSTRIDE, *bh = b_hh + 1 * BSTRIDE;
            void* args[] = { (void*)&wi, (void*)&wh, (void*)&bi, (void*)&bh,
                             (void*)&x, (void*)&rb, (void*)&t_next };
            launch_pdl((const void*)k_lstm<1>, g, b256, args);
        }
        {
            const float *wi = W_ih + 2 * WSTRIDE, *wh = W_hh + 2 * WSTRIDE;
            const float *bi = b_ih + 2 * BSTRIDE, *bh = b_hh + 2 * BSTRIDE;
            void* args[] = { (void*)&wi, (void*)&wh, (void*)&bi, (void*)&bh,
                             (void*)&x, (void*)&rb, (void*)&t_next };
            launch_pdl((const void*)k_lstm<2>, g, b256, args);
        }
    }
    {
        float* out = (float*)d_out;
        int n = out_size;
        void* args[] = { (void*)&out, (void*)&n };
        launch_pdl((const void*)k_out, dim3((out_size + 255) / 256), b256, args);
    }
}

// round 15
// speedup vs baseline: 1.4676x; 1.0703x over previous
#include <cuda_runtime.h>
#include <math.h>

#define T_STEPS 64
#define B_ 128
#define H_ 256
#define C_ 256
#define K_ 8
#define L_ 3
#define BK 1024
#define NEGV (-1e30f)

// ------------------------- device scratch (static, no allocs) ---------------
__device__ float g_WpT[H_ * C_];            // Wp transposed: [i][c]
__device__ float g_P0[C_ * 4 * H_];         // emb @ W_ih0^T + b_ih0 + b_hh0
__device__ float g_state[BK * H_];          // [B*K, H]
__device__ float g_h[2][L_][BK * H_];       // ping-pong hidden
__device__ float g_c[2][L_][BK * H_];       // ping-pong cell
__device__ float g_prefix[B_ * K_];
__device__ int   g_choices[B_ * K_ * T_STEPS];
__device__ int   g_src[BK];                 // gather source row (b*K + prev)
__device__ int   g_cls[BK];                 // chosen class per new beam row

// ------------------------- f32x2 packed helpers (sm_103a FFMA2) -------------
typedef unsigned long long u64;

__device__ __forceinline__ u64 fma2(u64 a, u64 b, u64 c) {
    u64 d;
    asm("fma.rn.f32x2 %0, %1, %2, %3;" : "=l"(d) : "l"(a), "l"(b), "l"(c));
    return d;
}
__device__ __forceinline__ u64 bcast2(float x) {
    u64 d; unsigned xi = __float_as_uint(x);
    asm("mov.b64 %0, {%1, %1};" : "=l"(d) : "r"(xi));
    return d;
}
__device__ __forceinline__ float lo2(u64 v) { return __uint_as_float((unsigned)v); }
__device__ __forceinline__ float hi2(u64 v) { return __uint_as_float((unsigned)(v >> 32)); }

// ------------------------- precise, fast-math-immune transcendentals --------
__device__ __forceinline__ float f_exp(float x) {
    const float LOG2E  = 1.4426950408889634f;
    const float LN2_HI = 0.693145751953125f;
    const float LN2_LO = 1.4286067653e-06f;
    float n = rintf(x * LOG2E);
    float r = fmaf(-n, LN2_HI, x);
    r = fmaf(-n, LN2_LO, r);
    float p = 1.9841269841e-4f;
    p = fmaf(p, r, 1.3888888889e-3f);
    p = fmaf(p, r, 8.3333333333e-3f);
    p = fmaf(p, r, 4.1666666667e-2f);
    p = fmaf(p, r, 1.6666666667e-1f);
    p = fmaf(p, r, 0.5f);
    p = fmaf(p, r, 1.0f);
    p = fmaf(p, r, 1.0f);
    int ni = (int)n;
    if (ni < -250) return 0.0f;
    if (ni >  250) ni = 250;
    int e1 = ni >> 1;
    int e2 = ni - e1;
    float s1 = __int_as_float((e1 + 127) << 23);
    float s2 = __int_as_float((e2 + 127) << 23);
    return p * s1 * s2;
}

__device__ __forceinline__ float f_tanh(float x) {
    float ax = fabsf(x);
    float t;
    if (ax < 0.25f) {
        float x2 = ax * ax;
        float p = 2.1869488536e-2f;
        p = fmaf(p, x2, -5.3968253968e-2f);
        p = fmaf(p, x2, 1.3333333333e-1f);
        p = fmaf(p, x2, -3.3333333333e-1f);
        t = fmaf(p * x2, ax, ax);
    } else {
        float e = f_exp(2.0f * ax);
        t = 1.0f - __fdiv_rn(2.0f, e + 1.0f);
    }
    return copysignf(t, x);
}

__device__ __forceinline__ float f_sig(float x) {
    return __fdiv_rn(1.0f, 1.0f + f_exp(-x));
}

// ------------------------- fused init: transpose + misc + P0 ----------------
__global__ __launch_bounds__(256) void k_init_combo(const float* __restrict__ x,
                                                    const float* __restrict__ Wp,
                                                    const float* __restrict__ emb,
                                                    const float* __restrict__ Wih0,
                                                    const float* __restrict__ bih0,
                                                    const float* __restrict__ bhh0) {
    int blk = blockIdx.x;
    if (blk < 1024) {
        int idx = blk * 256 + threadIdx.x;   // BK*H_ total
        int row = idx >> 8;
        int j = idx & 255;
        int b = row >> 3;
        g_state[idx] = x[b * H_ + j];
        if (idx < B_ * K_) g_prefix[idx] = ((idx & 7) == 0) ? 0.f : NEGV;
        if (idx < B_ * K_ * T_STEPS) g_choices[idx] = 0;
        return;
    }
    if (blk < 1280) {
        int idx = (blk - 1024) * 256 + threadIdx.x;   // H_*C_ total
        int i = idx >> 8, c = idx & 255;
        g_WpT[i * C_ + c] = Wp[c * H_ + i];
        return;
    }
    __shared__ float se[H_];
    int cidx = blk - 1280;
    se[threadIdx.x] = emb[cidx * H_ + threadIdx.x];
    __syncthreads();
    int t = threadIdx.x;
#pragma unroll
    for (int q = 0; q < 4; q++) {
        int n = q * H_ + t;
        const float4* wr = (const float4*)(Wih0 + (size_t)n * H_);
        float acc = 0.f;
#pragma unroll 8
        for (int k4 = 0; k4 < H_ / 4; k4++) {
            float4 w = wr[k4];
            float4 e = *(const float4*)&se[k4 * 4];
            acc += w.x * e.x + w.y * e.y + w.z * e.z + w.w * e.w;
        }
        g_P0[(size_t)cidx * (4 * H_) + n] = acc + bih0[n] + bhh0[n];
    }
}

// ------------------------- init LSTM, all 3 layers in one kernel ------------
__global__ __launch_bounds__(256) void k_init_lstm_all(const float* __restrict__ x,
                                                       const float* __restrict__ W_ih,
                                                       const float* __restrict__ b_ih,
                                                       const float* __restrict__ b_hh) {
    __shared__ float si[H_];
    int b = blockIdx.x;
    int t = threadIdx.x;
    const int WSTR = 4 * H_ * H_;
    const int BSTR = 4 * H_;
    for (int layer = 0; layer < L_; layer++) {
        const float* Wih = W_ih + (size_t)layer * WSTR;
        const float* bih = b_ih + (size_t)layer * BSTR;
        const float* bhh = b_hh + (size_t)layer * BSTR;
        const float* in = (layer == 0) ? (x + (size_t)b * H_)
                                       : (&g_h[0][layer - 1][0] + (size_t)(b * K_) * H_);
        si[t] = in[t];
        __syncthreads();
        float g4[4];
#pragma unroll
        for (int q = 0; q < 4; q++) {
            int n = q * H_ + t;
            const float4* wr = (const float4*)(Wih + (size_t)n * H_);
            float acc = 0.f;
#pragma unroll 8
            for (int k4 = 0; k4 < H_ / 4; k4++) {
                float4 w = wr[k4];
                float4 e = *(const float4*)&si[k4 * 4];
                acc += w.x * e.x + w.y * e.y + w.z * e.z + w.w * e.w;
            }
            g4[q] = acc + bih[n] + bhh[n];
        }
        float cn = f_sig(g4[0]) * f_tanh(g4[2]);
        float hn = f_sig(g4[3]) * f_tanh(cn);
#pragma unroll
        for (int kb = 0; kb < K_; kb++) {
            g_h[0][layer][((size_t)b * K_ + kb) * H_ + t] = hn;
            g_c[0][layer][((size_t)b * K_ + kb) * H_ + t] = cn;
        }
        __syncthreads();
    }
}

// ------------------------- projection + log_softmax + top-K -----------------
__global__ __launch_bounds__(256) void k_proj(const float* __restrict__ bp, int t) {
    __shared__ __align__(16) float s_state[K_][H_];
    __shared__ float s_pref[K_];
    __shared__ float s_red[8][K_];
    __shared__ float s_max[K_];
    __shared__ float s_lsum[K_];
    __shared__ float s_redv[8];
    __shared__ int   s_redi[8];
    __shared__ float s_topv[K_];
    __shared__ int   s_topi[K_];
    __shared__ int   s_prev[K_];
    __shared__ int   s_clss[K_];
    __shared__ int   s_ch[K_ * T_STEPS];

    int b = blockIdx.x;
    int tid = threadIdx.x;
    int warp = tid >> 5, lane = tid & 31;

    for (int u = tid; u < K_ * H_; u += 256)
        ((float*)s_state)[u] = g_state[(size_t)b * K_ * H_ + u];
    if (tid < K_) s_pref[tid] = g_prefix[b * K_ + tid];
    __syncthreads();

    int c = tid;
    float acc[K_];
#pragma unroll
    for (int k = 0; k < K_; k++) acc[k] = 0.f;
    for (int i0 = 0; i0 < H_; i0 += 4) {
        float4 sv[K_];
#pragma unroll
        for (int k = 0; k < K_; k++) sv[k] = *(const float4*)&s_state[k][i0];
        float w0 = g_WpT[(i0 + 0) * C_ + c];
        float w1 = g_WpT[(i0 + 1) * C_ + c];
        float w2 = g_WpT[(i0 + 2) * C_ + c];
        float w3 = g_WpT[(i0 + 3) * C_ + c];
#pragma unroll
        for (int k = 0; k < K_; k++) acc[k] += sv[k].x * w0;
#pragma unroll
        for (int k = 0; k < K_; k++) acc[k] += sv[k].y * w1;
#pragma unroll
        for (int k = 0; k < K_; k++) acc[k] += sv[k].z * w2;
#pragma unroll
        for (int k = 0; k < K_; k++) acc[k] += sv[k].w * w3;
    }
    float bb = bp[c];
#pragma unroll
    for (int k = 0; k < K_; k++) acc[k] += bb;

    // per-beam max
    {
        float m[K_];
#pragma unroll
        for (int k = 0; k < K_; k++) {
            float v = acc[k];
            for (int o = 16; o; o >>= 1) v = fmaxf(v, __shfl_xor_sync(0xffffffffu, v, o));
            m[k] = v;
        }
        if (lane == 0)
#pragma unroll
            for (int k = 0; k < K_; k++) s_red[warp][k] = m[k];
        __syncthreads();
        if (tid < K_) {
            float v = s_red[0][tid];
            for (int w2 = 1; w2 < 8; w2++) v = fmaxf(v, s_red[w2][tid]);
            s_max[tid] = v;
        }
        __syncthreads();
    }
    float mx[K_];
#pragma unroll
    for (int k = 0; k < K_; k++) mx[k] = s_max[k];
    // per-beam sum of exp (precise exp)
    {
        float s[K_];
#pragma unroll
        for (int k = 0; k < K_; k++) {
            float v = f_exp(acc[k] - mx[k]);
            for (int o = 16; o; o >>= 1) v += __shfl_xor_sync(0xffffffffu, v, o);
            s[k] = v;
        }
        __syncthreads();
        if (lane == 0)
#pragma unroll
            for (int k = 0; k < K_; k++) s_red[warp][k] = s[k];
        __syncthreads();
        if (tid < K_) {
            float v = 0.f;
            for (int w2 = 0; w2 < 8; w2++) v += s_red[w2][tid];
            s_lsum[tid] = (float)log((double)v);   // precise log
        }
        __syncthreads();
    }
    float jt[K_];
#pragma unroll
    for (int k = 0; k < K_; k++) jt[k] = s_pref[k] + ((acc[k] - mx[k]) - s_lsum[k]);

    // iterated block argmax (ties -> lowest flat idx, matching jax top_k)
    for (int it = 0; it < K_; it++) {
        float bv = -INFINITY;
        int bi = 0x7fffffff;
#pragma unroll
        for (int k = 0; k < K_; k++) {
            if (jt[k] > bv) { bv = jt[k]; bi = k * C_ + c; }
        }
        for (int o = 16; o; o >>= 1) {
            float ov = __shfl_xor_sync(0xffffffffu, bv, o);
            int   oi = __shfl_xor_sync(0xffffffffu, bi, o);
            if (ov > bv || (ov == bv && oi < bi)) { bv = ov; bi = oi; }
        }
        if (lane == 0) { s_redv[warp] = bv; s_redi[warp] = bi; }
        __syncthreads();
        if (tid == 0) {
            float fv = s_redv[0]; int fi = s_redi[0];
            for (int w2 = 1; w2 < 8; w2++)
                if (s_redv[w2] > fv || (s_redv[w2] == fv && s_redi[w2] < fi)) {
                    fv = s_redv[w2]; fi = s_redi[w2];
                }
            s_topv[it] = fv; s_topi[it] = fi;
        }
        __syncthreads();
        int sel = s_topi[it];
        if ((sel & (C_ - 1)) == c) jt[sel >> 8] = -INFINITY;
    }

    if (tid < K_) {
        int sel = s_topi[tid];
        int prev = sel >> 8;
        int cls = sel & (C_ - 1);
        g_prefix[b * K_ + tid] = s_topv[tid];
        g_src[b * K_ + tid] = b * K_ + prev;
        g_cls[b * K_ + tid] = cls;
        s_prev[tid] = prev;
        s_clss[tid] = cls;
    }
    __syncthreads();
    for (int u = tid; u < K_ * T_STEPS; u += 256) {
        int kq = u >> 6, tt = u & 63;
        s_ch[u] = g_choices[(b * K_ + s_prev[kq]) * T_STEPS + tt];
    }
    __syncthreads();
    for (int u = tid; u < K_ * T_STEPS; u += 256) {
        int kq = u >> 6, tt = u & 63;
        g_choices[(b * K_ + kq) * T_STEPS + tt] = (tt == t) ? s_clss[kq] : s_ch[u];
    }
}

// ------------------------- LSTM layer GEMM + gates --------------------------
// Tile: 128 rows x 64 gate-cols (R7 shape), grid 8x16, 256 threads.
// k-tiles DEEPENED to 32 (half the barriers, 6 float4 LDGs in flight per
// thread per tile). Inner fma2 ordering per output (k ascending, (g0,g1)/
// (g2,g3) pairing) identical to rounds 6-10 -> bit-exact.
template <int LAYER>
__global__ __launch_bounds__(256) void k_lstm(const float* __restrict__ Wih,
                                              const float* __restrict__ Whh,
                                              const float* __restrict__ bih,
                                              const float* __restrict__ bhh,
                                              const float* __restrict__ x,
                                              int rb, int t_next) {
    __shared__ __align__(16) float As[2][32][128];
    __shared__ __align__(16) float Ws[2][32][64];
    __shared__ int s_src[128];
    __shared__ int s_cls[128];

    const float* hcur = g_h[rb][LAYER];
    const float* ccur = g_c[rb][LAYER];
    float* hnxt = g_h[1 - rb][LAYER];
    float* cnxt = g_c[1 - rb][LAYER];
    const float* inp = (LAYER == 0) ? (const float*)0 : g_h[1 - rb][LAYER - 1];

    int tid = threadIdx.x;
    int rBase = blockIdx.x * 128;
    int jBase = blockIdx.y * 16;

    if (tid < 128) {
        s_src[tid] = g_src[rBase + tid];
        if (LAYER == 0) s_cls[tid] = g_cls[rBase + tid];
    }
    __syncthreads();

    // ---- staging indices (32-wide k-tiles) ----
    int arow = tid >> 1;            // 0..127: local A row (2 threads/row)
    int akq  = (tid & 1) * 16;      // k offset within 32-tile (0 or 16)
    int wrow = tid >> 2;            // 0..63: local W col (n_l = j_local*4+gate)
    int wkq  = (tid & 3) * 8;       // k offset (0,8,16,24)

    const float* aHid = hcur + (size_t)s_src[arow] * H_;
    const float* aIn  = (LAYER == 0) ? (const float*)0
                                     : inp + (size_t)(rBase + arow) * H_;
    const size_t wgrow = (size_t)((wrow & 3) * H_ + jBase + (wrow >> 2)) * H_;
    const float* wiP = Wih + wgrow;
    const float* whP = Whh + wgrow;

    const int KSTART = (LAYER == 0) ? 256 : 0;
    const int NT = (512 - KSTART) / 32;

    int tx = tid & 15, ty = tid >> 4;

    u64 acc[8][2];
#pragma unroll
    for (int r = 0; r < 8; r++) { acc[r][0] = 0ull; acc[r][1] = 0ull; }

    // ---- prologue: load tile 0 ----
    float4 a0, a1, a2, a3, w0, w1;
    {
        int k = KSTART + akq;
        const float* p = (LAYER > 0 && k < 256) ? (aIn + k) : (aHid + (k - 256));
        a0 = *(const float4*)p;       a1 = *(const float4*)(p + 4);
        a2 = *(const float4*)(p + 8); a3 = *(const float4*)(p + 12);
        int kw = KSTART + wkq;
        const float* q = (LAYER > 0 && kw < 256) ? (wiP + kw) : (whP + (kw - 256));
        w0 = *(const float4*)q; w1 = *(const float4*)(q + 4);
    }
    {
        As[0][akq + 0][arow]  = a0.x; As[0][akq + 1][arow]  = a0.y;
        As[0][akq + 2][arow]  = a0.z; As[0][akq + 3][arow]  = a0.w;
        As[0][akq + 4][arow]  = a1.x; As[0][akq + 5][arow]  = a1.y;
        As[0][akq + 6][arow]  = a1.z; As[0][akq + 7][arow]  = a1.w;
        As[0][akq + 8][arow]  = a2.x; As[0][akq + 9][arow]  = a2.y;
        As[0][akq + 10][arow] = a2.z; As[0][akq + 11][arow] = a2.w;
        As[0][akq + 12][arow] = a3.x; As[0][akq + 13][arow] = a3.y;
        As[0][akq + 14][arow] = a3.z; As[0][akq + 15][arow] = a3.w;
        Ws[0][wkq + 0][wrow] = w0.x; Ws[0][wkq + 1][wrow] = w0.y;
        Ws[0][wkq + 2][wrow] = w0.z; Ws[0][wkq + 3][wrow] = w0.w;
        Ws[0][wkq + 4][wrow] = w1.x; Ws[0][wkq + 5][wrow] = w1.y;
        Ws[0][wkq + 6][wrow] = w1.z; Ws[0][wkq + 7][wrow] = w1.w;
    }
    __syncthreads();

    for (int kt = 0; kt < NT; kt++) {
        int buf = kt & 1;
        bool more = (kt + 1 < NT);
        if (more) {
            int k = KSTART + (kt + 1) * 32 + akq;
            const float* p = (LAYER > 0 && k < 256) ? (aIn + k) : (aHid + (k - 256));
            a0 = *(const float4*)p;       a1 = *(const float4*)(p + 4);
            a2 = *(const float4*)(p + 8); a3 = *(const float4*)(p + 12);
            int kw = KSTART + (kt + 1) * 32 + wkq;
            const float* q = (LAYER > 0 && kw < 256) ? (wiP + kw) : (whP + (kw - 256));
            w0 = *(const float4*)q; w1 = *(const float4*)(q + 4);
        }
#pragma unroll
        for (int kk = 0; kk < 32; kk++) {
            float4 av0 = *(const float4*)&As[buf][kk][ty * 8];
            float4 av1 = *(const float4*)&As[buf][kk][ty * 8 + 4];
            ulonglong2 wv = *(const ulonglong2*)&Ws[buf][kk][tx * 4];
            u64 bb;
            bb = bcast2(av0.x); acc[0][0] = fma2(bb, wv.x, acc[0][0]); acc[0][1] = fma2(bb, wv.y, acc[0][1]);
            bb = bcast2(av0.y); acc[1][0] = fma2(bb, wv.x, acc[1][0]); acc[1][1] = fma2(bb, wv.y, acc[1][1]);
            bb = bcast2(av0.z); acc[2][0] = fma2(bb, wv.x, acc[2][0]); acc[2][1] = fma2(bb, wv.y, acc[2][1]);
            bb = bcast2(av0.w); acc[3][0] = fma2(bb, wv.x, acc[3][0]); acc[3][1] = fma2(bb, wv.y, acc[3][1]);
            bb = bcast2(av1.x); acc[4][0] = fma2(bb, wv.x, acc[4][0]); acc[4][1] = fma2(bb, wv.y, acc[4][1]);
            bb = bcast2(av1.y); acc[5][0] = fma2(bb, wv.x, acc[5][0]); acc[5][1] = fma2(bb, wv.y, acc[5][1]);
            bb = bcast2(av1.z); acc[6][0] = fma2(bb, wv.x, acc[6][0]); acc[6][1] = fma2(bb, wv.y, acc[6][1]);
            bb = bcast2(av1.w); acc[7][0] = fma2(bb, wv.x, acc[7][0]); acc[7][1] = fma2(bb, wv.y, acc[7][1]);
        }
        if (more) {
            int nb = buf ^ 1;
            As[nb][akq + 0][arow]  = a0.x; As[nb][akq + 1][arow]  = a0.y;
            As[nb][akq + 2][arow]  = a0.z; As[nb][akq + 3][arow]  = a0.w;
            As[nb][akq + 4][arow]  = a1.x; As[nb][akq + 5][arow]  = a1.y;
            As[nb][akq + 6][arow]  = a1.z; As[nb][akq + 7][arow]  = a1.w;
            As[nb][akq + 8][arow]  = a2.x; As[nb][akq + 9][arow]  = a2.y;
            As[nb][akq + 10][arow] = a2.z; As[nb][akq + 11][arow] = a2.w;
            As[nb][akq + 12][arow] = a3.x; As[nb][akq + 13][arow] = a3.y;
            As[nb][akq + 14][arow] = a3.z; As[nb][akq + 15][arow] = a3.w;
            Ws[nb][wkq + 0][wrow] = w0.x; Ws[nb][wkq + 1][wrow] = w0.y;
            Ws[nb][wkq + 2][wrow] = w0.z; Ws[nb][wkq + 3][wrow] = w0.w;
            Ws[nb][wkq + 4][wrow] = w1.x; Ws[nb][wkq + 5][wrow] = w1.y;
            Ws[nb][wkq + 6][wrow] = w1.z; Ws[nb][wkq + 7][wrow] = w1.w;
        }
        __syncthreads();
    }

    // ---- epilogue (expressions identical to rounds 6-10) ----
    int j = jBase + tx;
    float bias[4];
    if (LAYER > 0) {
#pragma unroll
        for (int q = 0; q < 4; q++) bias[q] = bih[q * H_ + j] + bhh[q * H_ + j];
    }
#pragma unroll
    for (int r = 0; r < 8; r++) {
        int rl = ty * 8 + r;
        int row_g = rBase + rl;
        int b = row_g >> 3;
        float gi = lo2(acc[r][0]), gf = hi2(acc[r][0]);
        float gg = lo2(acc[r][1]), go = hi2(acc[r][1]);
        if (LAYER == 0) {
            const float* p0 = g_P0 + (size_t)s_cls[rl] * (4 * H_);
            gi += p0[0 * H_ + j]; gf += p0[1 * H_ + j];
            gg += p0[2 * H_ + j]; go += p0[3 * H_ + j];
        } else {
            gi += bias[0]; gf += bias[1]; gg += bias[2]; go += bias[3];
        }
        float cold = ccur[(size_t)s_src[rl] * H_ + j];
        float cn = f_sig(gf) * cold + f_sig(gi) * f_tanh(gg);
        float hn = f_sig(go) * f_tanh(cn);
        cnxt[(size_t)row_g * H_ + j] = cn;
        hnxt[(size_t)row_g * H_ + j] = hn;
        if (LAYER == 2)
            g_state[(size_t)row_g * H_ + j] = hn + x[(size_t)t_next * B_ * H_ + b * H_ + j];
    }
}

// ------------------------- output ------------------------------------------
__global__ void k_out(float* __restrict__ out, int n) {
    int i = blockIdx.x * 256 + threadIdx.x;
    if (i >= n) return;
    if (i < B_ * K_ * T_STEPS) out[i] = (float)g_choices[i];
    else if (i < B_ * K_ * T_STEPS + B_ * K_) out[i] = g_prefix[i - B_ * K_ * T_STEPS];
    else out[i] = 0.f;
}

// ------------------------- host --------------------------------------------
extern "C" void kernel_launch(void* const* d_in, const int* in_sizes, int n_in,
                              void* d_out, int out_size) {
    const float* x    = (const float*)d_in[0];
    const float* emb  = (const float*)d_in[1];
    const float* W_ih = (const float*)d_in[2];
    const float* W_hh = (const float*)d_in[3];
    const float* b_ih = (const float*)d_in[4];
    const float* b_hh = (const float*)d_in[5];
    const float* Wp   = (const float*)d_in[6];
    const float* bp   = (const float*)d_in[7];

    const size_t WSTRIDE = 4 * H_ * H_;
    const size_t BSTRIDE = 4 * H_;

    k_init_combo<<<1536, 256>>>(x, Wp, emb, W_ih, b_ih, b_hh);
    k_init_lstm_all<<<B_, 256>>>(x, W_ih, b_ih, b_hh);

    dim3 g(8, 16);
    for (int t = 0; t < T_STEPS; t++) {
        int rb = t & 1;
        int t_next = (t + 1 < T_STEPS) ? (t + 1) : (T_STEPS - 1);
        k_proj<<<B_, 256>>>(bp, t);
        k_lstm<0><<<g, 256>>>(W_ih, W_hh, b_ih, b_hh, x, rb, t_next);
        k_lstm<1><<<g, 256>>>(W_ih + 1 * WSTRIDE, W_hh + 1 * WSTRIDE,
                              b_ih + 1 * BSTRIDE, b_hh + 1 * BSTRIDE,
                              x, rb, t_next);
        k_lstm<2><<<g, 256>>>(W_ih + 2 * WSTRIDE, W_hh + 2 * WSTRIDE,
                              b_ih + 2 * BSTRIDE, b_hh + 2 * BSTRIDE,
                              x, rb, t_next);
    }
    k_out<<<(out_size + 255) / 256, 256>>>((float*)d_out, out_size);
}

// round 16
// speedup vs baseline: 1.5235x; 1.0381x over previous
#include <cuda_runtime.h>
#include <math.h>

#define T_STEPS 64
#define B_ 128
#define H_ 256
#define C_ 256
#define K_ 8
#define L_ 3
#define BK 1024
#define NEGV (-1e30f)

// ------------------------- device scratch (static, no allocs) ---------------
__device__ float g_WpT[H_ * C_];            // Wp transposed: [i][c]
__device__ float g_P0[C_ * 4 * H_];         // emb @ W_ih0^T + b_ih0 + b_hh0
__device__ float g_Ghh0[BK * 1024];         // h0 @ Whh0^T (ungathered), [row][j*4+gate]
__device__ float g_state[BK * H_];          // [B*K, H]
__device__ float g_h[2][L_][BK * H_];       // ping-pong hidden
__device__ float g_c[2][L_][BK * H_];       // ping-pong cell
__device__ float g_prefix[B_ * K_];
__device__ int   g_choices[B_ * K_ * T_STEPS];
__device__ int   g_src[BK];                 // gather source row (b*K + prev)
__device__ int   g_cls[BK];                 // chosen class per new beam row

// ------------------------- f32x2 packed helpers (sm_103a FFMA2) -------------
typedef unsigned long long u64;

__device__ __forceinline__ u64 fma2(u64 a, u64 b, u64 c) {
    u64 d;
    asm("fma.rn.f32x2 %0, %1, %2, %3;" : "=l"(d) : "l"(a), "l"(b), "l"(c));
    return d;
}
__device__ __forceinline__ u64 bcast2(float x) {
    u64 d; unsigned xi = __float_as_uint(x);
    asm("mov.b64 %0, {%1, %1};" : "=l"(d) : "r"(xi));
    return d;
}
__device__ __forceinline__ float lo2(u64 v) { return __uint_as_float((unsigned)v); }
__device__ __forceinline__ float hi2(u64 v) { return __uint_as_float((unsigned)(v >> 32)); }

// ------------------------- precise, fast-math-immune transcendentals --------
__device__ __forceinline__ float f_exp(float x) {
    const float LOG2E  = 1.4426950408889634f;
    const float LN2_HI = 0.693145751953125f;
    const float LN2_LO = 1.4286067653e-06f;
    float n = rintf(x * LOG2E);
    float r = fmaf(-n, LN2_HI, x);
    r = fmaf(-n, LN2_LO, r);
    float p = 1.9841269841e-4f;
    p = fmaf(p, r, 1.3888888889e-3f);
    p = fmaf(p, r, 8.3333333333e-3f);
    p = fmaf(p, r, 4.1666666667e-2f);
    p = fmaf(p, r, 1.6666666667e-1f);
    p = fmaf(p, r, 0.5f);
    p = fmaf(p, r, 1.0f);
    p = fmaf(p, r, 1.0f);
    int ni = (int)n;
    if (ni < -250) return 0.0f;
    if (ni >  250) ni = 250;
    int e1 = ni >> 1;
    int e2 = ni - e1;
    float s1 = __int_as_float((e1 + 127) << 23);
    float s2 = __int_as_float((e2 + 127) << 23);
    return p * s1 * s2;
}

__device__ __forceinline__ float f_tanh(float x) {
    float ax = fabsf(x);
    float t;
    if (ax < 0.25f) {
        float x2 = ax * ax;
        float p = 2.1869488536e-2f;
        p = fmaf(p, x2, -5.3968253968e-2f);
        p = fmaf(p, x2, 1.3333333333e-1f);
        p = fmaf(p, x2, -3.3333333333e-1f);
        t = fmaf(p * x2, ax, ax);
    } else {
        float e = f_exp(2.0f * ax);
        t = 1.0f - __fdiv_rn(2.0f, e + 1.0f);
    }
    return copysignf(t, x);
}

__device__ __forceinline__ float f_sig(float x) {
    return __fdiv_rn(1.0f, 1.0f + f_exp(-x));
}

// ------------------------- fused init: transpose + misc + P0 ----------------
__global__ __launch_bounds__(256) void k_init_combo(const float* __restrict__ x,
                                                    const float* __restrict__ Wp,
                                                    const float* __restrict__ emb,
                                                    const float* __restrict__ Wih0,
                                                    const float* __restrict__ bih0,
                                                    const float* __restrict__ bhh0) {
    int blk = blockIdx.x;
    if (blk < 1024) {
        int idx = blk * 256 + threadIdx.x;   // BK*H_ total
        int row = idx >> 8;
        int j = idx & 255;
        int b = row >> 3;
        g_state[idx] = x[b * H_ + j];
        if (idx < B_ * K_) g_prefix[idx] = ((idx & 7) == 0) ? 0.f : NEGV;
        if (idx < B_ * K_ * T_STEPS) g_choices[idx] = 0;
        return;
    }
    if (blk < 1280) {
        int idx = (blk - 1024) * 256 + threadIdx.x;   // H_*C_ total
        int i = idx >> 8, c = idx & 255;
        g_WpT[i * C_ + c] = Wp[c * H_ + i];
        return;
    }
    __shared__ float se[H_];
    int cidx = blk - 1280;
    se[threadIdx.x] = emb[cidx * H_ + threadIdx.x];
    __syncthreads();
    int t = threadIdx.x;
#pragma unroll
    for (int q = 0; q < 4; q++) {
        int n = q * H_ + t;
        const float4* wr = (const float4*)(Wih0 + (size_t)n * H_);
        float acc = 0.f;
#pragma unroll 8
        for (int k4 = 0; k4 < H_ / 4; k4++) {
            float4 w = wr[k4];
            float4 e = *(const float4*)&se[k4 * 4];
            acc += w.x * e.x + w.y * e.y + w.z * e.z + w.w * e.w;
        }
        g_P0[(size_t)cidx * (4 * H_) + n] = acc + bih0[n] + bhh0[n];
    }
}

// ------------------------- init LSTM, all 3 layers in one kernel ------------
__global__ __launch_bounds__(256) void k_init_lstm_all(const float* __restrict__ x,
                                                       const float* __restrict__ W_ih,
                                                       const float* __restrict__ b_ih,
                                                       const float* __restrict__ b_hh) {
    __shared__ float si[H_];
    int b = blockIdx.x;
    int t = threadIdx.x;
    const int WSTR = 4 * H_ * H_;
    const int BSTR = 4 * H_;
    for (int layer = 0; layer < L_; layer++) {
        const float* Wih = W_ih + (size_t)layer * WSTR;
        const float* bih = b_ih + (size_t)layer * BSTR;
        const float* bhh = b_hh + (size_t)layer * BSTR;
        const float* in = (layer == 0) ? (x + (size_t)b * H_)
                                       : (&g_h[0][layer - 1][0] + (size_t)(b * K_) * H_);
        si[t] = in[t];
        __syncthreads();
        float g4[4];
#pragma unroll
        for (int q = 0; q < 4; q++) {
            int n = q * H_ + t;
            const float4* wr = (const float4*)(Wih + (size_t)n * H_);
            float acc = 0.f;
#pragma unroll 8
            for (int k4 = 0; k4 < H_ / 4; k4++) {
                float4 w = wr[k4];
                float4 e = *(const float4*)&si[k4 * 4];
                acc += w.x * e.x + w.y * e.y + w.z * e.z + w.w * e.w;
            }
            g4[q] = acc + bih[n] + bhh[n];
        }
        float cn = f_sig(g4[0]) * f_tanh(g4[2]);
        float hn = f_sig(g4[3]) * f_tanh(cn);
#pragma unroll
        for (int kb = 0; kb < K_; kb++) {
            g_h[0][layer][((size_t)b * K_ + kb) * H_ + t] = hn;
            g_c[0][layer][((size_t)b * K_ + kb) * H_ + t] = cn;
        }
        __syncthreads();
    }
}

// ------------------------- Ghh0 GEMM body (bit-exact old-L0 chain) ----------
// Computes Ghh0[rBase..rBase+127][jB*?] = h0 @ Whh0^T with EXACTLY the same
// staging + fma2 chain as the old layer-0 k_lstm mainloop (32-deep k-tiles,
// KSTART=256 branch). Rows ungathered; gather(h)@W == gather(h@W) row-wise.
#define GHH0_BODY(H0PTR, WHH0, RBASE, JB)                                        \
    {                                                                            \
        int arow = tid >> 1;                                                     \
        int akq  = (tid & 1) * 16;                                               \
        int wrow = tid >> 2;                                                     \
        int wkq  = (tid & 3) * 8;                                                \
        const float* aHid = (H0PTR) + (size_t)((RBASE) + arow) * H_;             \
        const size_t wgrow = (size_t)((wrow & 3) * H_ + (JB) + (wrow >> 2)) * H_;\
        const float* whP = (WHH0) + wgrow;                                       \
        int tx = tid & 15, ty = tid >> 4;                                        \
        u64 acc[8][2];                                                           \
        _Pragma("unroll")                                                        \
        for (int r = 0; r < 8; r++) { acc[r][0] = 0ull; acc[r][1] = 0ull; }      \
        float4 a0, a1, a2, a3, w0, w1;                                           \
        {                                                                        \
            const float* p = aHid + akq;                                         \
            a0 = *(const float4*)p;       a1 = *(const float4*)(p + 4);          \
            a2 = *(const float4*)(p + 8); a3 = *(const float4*)(p + 12);         \
            const float* q = whP + wkq;                                          \
            w0 = *(const float4*)q; w1 = *(const float4*)(q + 4);                \
        }                                                                        \
        As[0][akq + 0][arow]  = a0.x; As[0][akq + 1][arow]  = a0.y;              \
        As[0][akq + 2][arow]  = a0.z; As[0][akq + 3][arow]  = a0.w;              \
        As[0][akq + 4][arow]  = a1.x; As[0][akq + 5][arow]  = a1.y;              \
        As[0][akq + 6][arow]  = a1.z; As[0][akq + 7][arow]  = a1.w;              \
        As[0][akq + 8][arow]  = a2.x; As[0][akq + 9][arow]  = a2.y;              \
        As[0][akq + 10][arow] = a2.z; As[0][akq + 11][arow] = a2.w;              \
        As[0][akq + 12][arow] = a3.x; As[0][akq + 13][arow] = a3.y;              \
        As[0][akq + 14][arow] = a3.z; As[0][akq + 15][arow] = a3.w;              \
        Ws[0][wkq + 0][wrow] = w0.x; Ws[0][wkq + 1][wrow] = w0.y;                \
        Ws[0][wkq + 2][wrow] = w0.z; Ws[0][wkq + 3][wrow] = w0.w;                \
        Ws[0][wkq + 4][wrow] = w1.x; Ws[0][wkq + 5][wrow] = w1.y;                \
        Ws[0][wkq + 6][wrow] = w1.z; Ws[0][wkq + 7][wrow] = w1.w;                \
        __syncthreads();                                                         \
        for (int kt = 0; kt < 8; kt++) {                                         \
            int buf = kt & 1;                                                    \
            bool more = (kt + 1 < 8);                                            \
            if (more) {                                                          \
                const float* p = aHid + (kt + 1) * 32 + akq;                     \
                a0 = *(const float4*)p;       a1 = *(const float4*)(p + 4);      \
                a2 = *(const float4*)(p + 8); a3 = *(const float4*)(p + 12);     \
                const float* q = whP + (kt + 1) * 32 + wkq;                      \
                w0 = *(const float4*)q; w1 = *(const float4*)(q + 4);            \
            }                                                                    \
            _Pragma("unroll")                                                    \
            for (int kk = 0; kk < 32; kk++) {                                    \
                float4 av0 = *(const float4*)&As[buf][kk][ty * 8];               \
                float4 av1 = *(const float4*)&As[buf][kk][ty * 8 + 4];           \
                ulonglong2 wv = *(const ulonglong2*)&Ws[buf][kk][tx * 4];        \
                u64 bb;                                                          \
                bb = bcast2(av0.x); acc[0][0] = fma2(bb, wv.x, acc[0][0]); acc[0][1] = fma2(bb, wv.y, acc[0][1]); \
                bb = bcast2(av0.y); acc[1][0] = fma2(bb, wv.x, acc[1][0]); acc[1][1] = fma2(bb, wv.y, acc[1][1]); \
                bb = bcast2(av0.z); acc[2][0] = fma2(bb, wv.x, acc[2][0]); acc[2][1] = fma2(bb, wv.y, acc[2][1]); \
                bb = bcast2(av0.w); acc[3][0] = fma2(bb, wv.x, acc[3][0]); acc[3][1] = fma2(bb, wv.y, acc[3][1]); \
                bb = bcast2(av1.x); acc[4][0] = fma2(bb, wv.x, acc[4][0]); acc[4][1] = fma2(bb, wv.y, acc[4][1]); \
                bb = bcast2(av1.y); acc[5][0] = fma2(bb, wv.x, acc[5][0]); acc[5][1] = fma2(bb, wv.y, acc[5][1]); \
                bb = bcast2(av1.z); acc[6][0] = fma2(bb, wv.x, acc[6][0]); acc[6][1] = fma2(bb, wv.y, acc[6][1]); \
                bb = bcast2(av1.w); acc[7][0] = fma2(bb, wv.x, acc[7][0]); acc[7][1] = fma2(bb, wv.y, acc[7][1]); \
            }                                                                    \
            if (more) {                                                          \
                int nb = buf ^ 1;                                                \
                As[nb][akq + 0][arow]  = a0.x; As[nb][akq + 1][arow]  = a0.y;    \
                As[nb][akq + 2][arow]  = a0.z; As[nb][akq + 3][arow]  = a0.w;    \
                As[nb][akq + 4][arow]  = a1.x; As[nb][akq + 5][arow]  = a1.y;    \
                As[nb][akq + 6][arow]  = a1.z; As[nb][akq + 7][arow]  = a1.w;    \
                As[nb][akq + 8][arow]  = a2.x; As[nb][akq + 9][arow]  = a2.y;    \
                As[nb][akq + 10][arow] = a2.z; As[nb][akq + 11][arow] = a2.w;    \
                As[nb][akq + 12][arow] = a3.x; As[nb][akq + 13][arow] = a3.y;    \
                As[nb][akq + 14][arow] = a3.z; As[nb][akq + 15][arow] = a3.w;    \
                Ws[nb][wkq + 0][wrow] = w0.x; Ws[nb][wkq + 1][wrow] = w0.y;      \
                Ws[nb][wkq + 2][wrow] = w0.z; Ws[nb][wkq + 3][wrow] = w0.w;      \
                Ws[nb][wkq + 4][wrow] = w1.x; Ws[nb][wkq + 5][wrow] = w1.y;      \
                Ws[nb][wkq + 6][wrow] = w1.z; Ws[nb][wkq + 7][wrow] = w1.w;      \
            }                                                                    \
            __syncthreads();                                                     \
        }                                                                        \
        _Pragma("unroll")                                                        \
        for (int r = 0; r < 8; r++) {                                            \
            int row = (RBASE) + ty * 8 + r;                                      \
            float4 v;                                                            \
            v.x = lo2(acc[r][0]); v.y = hi2(acc[r][0]);                          \
            v.z = lo2(acc[r][1]); v.w = hi2(acc[r][1]);                          \
            *(float4*)&g_Ghh0[(size_t)row * 1024 + ((JB) + tx) * 4] = v;         \
        }                                                                        \
    }

// ------------------------- standalone Ghh0 (for t=0, from init h) ------------
__global__ __launch_bounds__(256) void k_ghh0_init(const float* __restrict__ Whh0) {
    __shared__ __align__(16) float As[2][32][128];
    __shared__ __align__(16) float Ws[2][32][64];
    int tid = threadIdx.x;
    const float* h0 = &g_h[0][0][0];
    GHH0_BODY(h0, Whh0, blockIdx.x * 128, blockIdx.y * 16)
}

// ------------------- projection + top-K + fused LSTM-0 epilogue -------------
__global__ __launch_bounds__(256) void k_proj(const float* __restrict__ bp, int t, int rb) {
    __shared__ __align__(16) float s_state[K_][H_];
    __shared__ float s_pref[K_];
    __shared__ float s_red[8][K_];
    __shared__ float s_max[K_];
    __shared__ float s_lsum[K_];
    __shared__ float s_redv[8];
    __shared__ int   s_redi[8];
    __shared__ float s_topv[K_];
    __shared__ int   s_topi[K_];
    __shared__ int   s_prev[K_];
    __shared__ int   s_clss[K_];
    __shared__ int   s_ch[K_ * T_STEPS];

    int b = blockIdx.x;
    int tid = threadIdx.x;
    int warp = tid >> 5, lane = tid & 31;

    for (int u = tid; u < K_ * H_; u += 256)
        ((float*)s_state)[u] = g_state[(size_t)b * K_ * H_ + u];
    if (tid < K_) s_pref[tid] = g_prefix[b * K_ + tid];
    __syncthreads();

    int c = tid;
    float acc[K_];
#pragma unroll
    for (int k = 0; k < K_; k++) acc[k] = 0.f;
    for (int i0 = 0; i0 < H_; i0 += 4) {
        float4 sv[K_];
#pragma unroll
        for (int k = 0; k < K_; k++) sv[k] = *(const float4*)&s_state[k][i0];
        float w0 = g_WpT[(i0 + 0) * C_ + c];
        float w1 = g_WpT[(i0 + 1) * C_ + c];
        float w2 = g_WpT[(i0 + 2) * C_ + c];
        float w3 = g_WpT[(i0 + 3) * C_ + c];
#pragma unroll
        for (int k = 0; k < K_; k++) acc[k] += sv[k].x * w0;
#pragma unroll
        for (int k = 0; k < K_; k++) acc[k] += sv[k].y * w1;
#pragma unroll
        for (int k = 0; k < K_; k++) acc[k] += sv[k].z * w2;
#pragma unroll
        for (int k = 0; k < K_; k++) acc[k] += sv[k].w * w3;
    }
    float bb = bp[c];
#pragma unroll
    for (int k = 0; k < K_; k++) acc[k] += bb;

    // per-beam max
    {
        float m[K_];
#pragma unroll
        for (int k = 0; k < K_; k++) {
            float v = acc[k];
            for (int o = 16; o; o >>= 1) v = fmaxf(v, __shfl_xor_sync(0xffffffffu, v, o));
            m[k] = v;
        }
        if (lane == 0)
#pragma unroll
            for (int k = 0; k < K_; k++) s_red[warp][k] = m[k];
        __syncthreads();
        if (tid < K_) {
            float v = s_red[0][tid];
            for (int w2 = 1; w2 < 8; w2++) v = fmaxf(v, s_red[w2][tid]);
            s_max[tid] = v;
        }
        __syncthreads();
    }
    float mx[K_];
#pragma unroll
    for (int k = 0; k < K_; k++) mx[k] = s_max[k];
    // per-beam sum of exp (precise exp)
    {
        float s[K_];
#pragma unroll
        for (int k = 0; k < K_; k++) {
            float v = f_exp(acc[k] - mx[k]);
            for (int o = 16; o; o >>= 1) v += __shfl_xor_sync(0xffffffffu, v, o);
            s[k] = v;
        }
        __syncthreads();
        if (lane == 0)
#pragma unroll
            for (int k = 0; k < K_; k++) s_red[warp][k] = s[k];
        __syncthreads();
        if (tid < K_) {
            float v = 0.f;
            for (int w2 = 0; w2 < 8; w2++) v += s_red[w2][tid];
            s_lsum[tid] = (float)log((double)v);   // precise log
        }
        __syncthreads();
    }
    float jt[K_];
#pragma unroll
    for (int k = 0; k < K_; k++) jt[k] = s_pref[k] + ((acc[k] - mx[k]) - s_lsum[k]);

    // iterated block argmax (ties -> lowest flat idx, matching jax top_k)
    for (int it = 0; it < K_; it++) {
        float bv = -INFINITY;
        int bi = 0x7fffffff;
#pragma unroll
        for (int k = 0; k < K_; k++) {
            if (jt[k] > bv) { bv = jt[k]; bi = k * C_ + c; }
        }
        for (int o = 16; o; o >>= 1) {
            float ov = __shfl_xor_sync(0xffffffffu, bv, o);
            int   oi = __shfl_xor_sync(0xffffffffu, bi, o);
            if (ov > bv || (ov == bv && oi < bi)) { bv = ov; bi = oi; }
        }
        if (lane == 0) { s_redv[warp] = bv; s_redi[warp] = bi; }
        __syncthreads();
        if (tid == 0) {
            float fv = s_redv[0]; int fi = s_redi[0];
            for (int w2 = 1; w2 < 8; w2++)
                if (s_redv[w2] > fv || (s_redv[w2] == fv && s_redi[w2] < fi)) {
                    fv = s_redv[w2]; fi = s_redi[w2];
                }
            s_topv[it] = fv; s_topi[it] = fi;
        }
        __syncthreads();
        int sel = s_topi[it];
        if ((sel & (C_ - 1)) == c) jt[sel >> 8] = -INFINITY;
    }

    if (tid < K_) {
        int sel = s_topi[tid];
        int prev = sel >> 8;
        int cls = sel & (C_ - 1);
        g_prefix[b * K_ + tid] = s_topv[tid];
        g_src[b * K_ + tid] = b * K_ + prev;
        g_cls[b * K_ + tid] = cls;
        s_prev[tid] = prev;
        s_clss[tid] = cls;
    }
    __syncthreads();
    for (int u = tid; u < K_ * T_STEPS; u += 256) {
        int kq = u >> 6, tt = u & 63;
        s_ch[u] = g_choices[(b * K_ + s_prev[kq]) * T_STEPS + tt];
    }
    __syncthreads();
    for (int u = tid; u < K_ * T_STEPS; u += 256) {
        int kq = u >> 6, tt = u & 63;
        g_choices[(b * K_ + kq) * T_STEPS + tt] = (tt == t) ? s_clss[kq] : s_ch[u];
    }

    // ---- fused LSTM layer-0 epilogue (bit-exact: Ghh0 gather + P0 + gates) ----
    {
        int j = tid;                    // 0..255
        const float* c0cur = g_c[rb][0];
        float* h0nxt = g_h[1 - rb][0];
        float* c0nxt = g_c[1 - rb][0];
#pragma unroll
        for (int kb = 0; kb < K_; kb++) {
            int row = b * K_ + kb;
            int srcrow = b * K_ + s_prev[kb];
            float4 gv = *(const float4*)&g_Ghh0[(size_t)srcrow * 1024 + j * 4];
            const float* p0 = g_P0 + (size_t)s_clss[kb] * (4 * H_);
            float gi = gv.x; gi += p0[0 * H_ + j];
            float gf = gv.y; gf += p0[1 * H_ + j];
            float gg = gv.z; gg += p0[2 * H_ + j];
            float go = gv.w; go += p0[3 * H_ + j];
            float cold = c0cur[(size_t)srcrow * H_ + j];
            float cn = f_sig(gf) * cold + f_sig(gi) * f_tanh(gg);
            float hn = f_sig(go) * f_tanh(cn);
            c0nxt[(size_t)row * H_ + j] = cn;
            h0nxt[(size_t)row * H_ + j] = hn;
        }
    }
}

// ------------------------- LSTM layer GEMM + gates (layers 1,2) -------------
// R15 32-deep version. For LAYER==2 the grid is (8,32): blocks with y>=16 run
// the Ghh0-for-next-step role (reads h0 just written by k_proj this step).
template <int LAYER>
__global__ __launch_bounds__(256) void k_lstm(const float* __restrict__ Wih,
                                              const float* __restrict__ Whh,
                                              const float* __restrict__ bih,
                                              const float* __restrict__ bhh,
                                              const float* __restrict__ x,
                                              int rb, int t_next,
                                              const float* __restrict__ Whh0) {
    __shared__ __align__(16) float As[2][32][128];
    __shared__ __align__(16) float Ws[2][32][64];
    __shared__ int s_src[128];

    int tid = threadIdx.x;
    int rBase = blockIdx.x * 128;

    if (LAYER == 2 && blockIdx.y >= 16) {
        // Ghh0 role: h0(t) = g_h[1-rb][0] (written by k_proj this step)
        const float* h0 = &g_h[1 - rb][0][0];
        GHH0_BODY(h0, Whh0, rBase, (int)(blockIdx.y - 16) * 16)
        return;
    }

    const float* hcur = g_h[rb][LAYER];
    const float* ccur = g_c[rb][LAYER];
    float* hnxt = g_h[1 - rb][LAYER];
    float* cnxt = g_c[1 - rb][LAYER];
    const float* inp = g_h[1 - rb][LAYER - 1];

    int jBase = blockIdx.y * 16;

    if (tid < 128) s_src[tid] = g_src[rBase + tid];
    __syncthreads();

    int arow = tid >> 1;
    int akq  = (tid & 1) * 16;
    int wrow = tid >> 2;
    int wkq  = (tid & 3) * 8;

    const float* aHid = hcur + (size_t)s_src[arow] * H_;
    const float* aIn  = inp + (size_t)(rBase + arow) * H_;
    const size_t wgrow = (size_t)((wrow & 3) * H_ + jBase + (wrow >> 2)) * H_;
    const float* wiP = Wih + wgrow;
    const float* whP = Whh + wgrow;

    const int NT = 16;   // K=512 / 32

    int tx = tid & 15, ty = tid >> 4;

    u64 acc[8][2];
#pragma unroll
    for (int r = 0; r < 8; r++) { acc[r][0] = 0ull; acc[r][1] = 0ull; }

    float4 a0, a1, a2, a3, w0, w1;
    {
        int k = akq;
        const float* p = (k < 256) ? (aIn + k) : (aHid + (k - 256));
        a0 = *(const float4*)p;       a1 = *(const float4*)(p + 4);
        a2 = *(const float4*)(p + 8); a3 = *(const float4*)(p + 12);
        int kw = wkq;
        const float* q = (kw < 256) ? (wiP + kw) : (whP + (kw - 256));
        w0 = *(const float4*)q; w1 = *(const float4*)(q + 4);
    }
    {
        As[0][akq + 0][arow]  = a0.x; As[0][akq + 1][arow]  = a0.y;
        As[0][akq + 2][arow]  = a0.z; As[0][akq + 3][arow]  = a0.w;
        As[0][akq + 4][arow]  = a1.x; As[0][akq + 5][arow]  = a1.y;
        As[0][akq + 6][arow]  = a1.z; As[0][akq + 7][arow]  = a1.w;
        As[0][akq + 8][arow]  = a2.x; As[0][akq + 9][arow]  = a2.y;
        As[0][akq + 10][arow] = a2.z; As[0][akq + 11][arow] = a2.w;
        As[0][akq + 12][arow] = a3.x; As[0][akq + 13][arow] = a3.y;
        As[0][akq + 14][arow] = a3.z; As[0][akq + 15][arow] = a3.w;
        Ws[0][wkq + 0][wrow] = w0.x; Ws[0][wkq + 1][wrow] = w0.y;
        Ws[0][wkq + 2][wrow] = w0.z; Ws[0][wkq + 3][wrow] = w0.w;
        Ws[0][wkq + 4][wrow] = w1.x; Ws[0][wkq + 5][wrow] = w1.y;
        Ws[0][wkq + 6][wrow] = w1.z; Ws[0][wkq + 7][wrow] = w1.w;
    }
    __syncthreads();

    for (int kt = 0; kt < NT; kt++) {
        int buf = kt & 1;
        bool more = (kt + 1 < NT);
        if (more) {
            int k = (kt + 1) * 32 + akq;
            const float* p = (k < 256) ? (aIn + k) : (aHid + (k - 256));
            a0 = *(const float4*)p;       a1 = *(const float4*)(p + 4);
            a2 = *(const float4*)(p + 8); a3 = *(const float4*)(p + 12);
            int kw = (kt + 1) * 32 + wkq;
            const float* q = (kw < 256) ? (wiP + kw) : (whP + (kw - 256));
            w0 = *(const float4*)q; w1 = *(const float4*)(q + 4);
        }
#pragma unroll
        for (int kk = 0; kk < 32; kk++) {
            float4 av0 = *(const float4*)&As[buf][kk][ty * 8];
            float4 av1 = *(const float4*)&As[buf][kk][ty * 8 + 4];
            ulonglong2 wv = *(const ulonglong2*)&Ws[buf][kk][tx * 4];
            u64 bb;
            bb = bcast2(av0.x); acc[0][0] = fma2(bb, wv.x, acc[0][0]); acc[0][1] = fma2(bb, wv.y, acc[0][1]);
            bb = bcast2(av0.y); acc[1][0] = fma2(bb, wv.x, acc[1][0]); acc[1][1] = fma2(bb, wv.y, acc[1][1]);
            bb = bcast2(av0.z); acc[2][0] = fma2(bb, wv.x, acc[2][0]); acc[2][1] = fma2(bb, wv.y, acc[2][1]);
            bb = bcast2(av0.w); acc[3][0] = fma2(bb, wv.x, acc[3][0]); acc[3][1] = fma2(bb, wv.y, acc[3][1]);
            bb = bcast2(av1.x); acc[4][0] = fma2(bb, wv.x, acc[4][0]); acc[4][1] = fma2(bb, wv.y, acc[4][1]);
            bb = bcast2(av1.y); acc[5][0] = fma2(bb, wv.x, acc[5][0]); acc[5][1] = fma2(bb, wv.y, acc[5][1]);
            bb = bcast2(av1.z); acc[6][0] = fma2(bb, wv.x, acc[6][0]); acc[6][1] = fma2(bb, wv.y, acc[6][1]);
            bb = bcast2(av1.w); acc[7][0] = fma2(bb, wv.x, acc[7][0]); acc[7][1] = fma2(bb, wv.y, acc[7][1]);
        }
        if (more) {
            int nb = buf ^ 1;
            As[nb][akq + 0][arow]  = a0.x; As[nb][akq + 1][arow]  = a0.y;
            As[nb][akq + 2][arow]  = a0.z; As[nb][akq + 3][arow]  = a0.w;
            As[nb][akq + 4][arow]  = a1.x; As[nb][akq + 5][arow]  = a1.y;
            As[nb][akq + 6][arow]  = a1.z; As[nb][akq + 7][arow]  = a1.w;
            As[nb][akq + 8][arow]  = a2.x; As[nb][akq + 9][arow]  = a2.y;
            As[nb][akq + 10][arow] = a2.z; As[nb][akq + 11][arow] = a2.w;
            As[nb][akq + 12][arow] = a3.x; As[nb][akq + 13][arow] = a3.y;
            As[nb][akq + 14][arow] = a3.z; As[nb][akq + 15][arow] = a3.w;
            Ws[nb][wkq + 0][wrow] = w0.x; Ws[nb][wkq + 1][wrow] = w0.y;
            Ws[nb][wkq + 2][wrow] = w0.z; Ws[nb][wkq + 3][wrow] = w0.w;
            Ws[nb][wkq + 4][wrow] = w1.x; Ws[nb][wkq + 5][wrow] = w1.y;
            Ws[nb][wkq + 6][wrow] = w1.z; Ws[nb][wkq + 7][wrow] = w1.w;
        }
        __syncthreads();
    }

    int j = jBase + tx;
    float bias[4];
#pragma unroll
    for (int q = 0; q < 4; q++) bias[q] = bih[q * H_ + j] + bhh[q * H_ + j];
#pragma unroll
    for (int r = 0; r < 8; r++) {
        int rl = ty * 8 + r;
        int row_g = rBase + rl;
        int b = row_g >> 3;
        float gi = lo2(acc[r][0]), gf = hi2(acc[r][0]);
        float gg = lo2(acc[r][1]), go = hi2(acc[r][1]);
        gi += bias[0]; gf += bias[1]; gg += bias[2]; go += bias[3];
        float cold = ccur[(size_t)s_src[rl] * H_ + j];
        float cn = f_sig(gf) * cold + f_sig(gi) * f_tanh(gg);
        float hn = f_sig(go) * f_tanh(cn);
        cnxt[(size_t)row_g * H_ + j] = cn;
        hnxt[(size_t)row_g * H_ + j] = hn;
        if (LAYER == 2)
            g_state[(size_t)row_g * H_ + j] = hn + x[(size_t)t_next * B_ * H_ + b * H_ + j];
    }
}

// ------------------------- output ------------------------------------------
__global__ void k_out(float* __restrict__ out, int n) {
    int i = blockIdx.x * 256 + threadIdx.x;
    if (i >= n) return;
    if (i < B_ * K_ * T_STEPS) out[i] = (float)g_choices[i];
    else if (i < B_ * K_ * T_STEPS + B_ * K_) out[i] = g_prefix[i - B_ * K_ * T_STEPS];
    else out[i] = 0.f;
}

// ------------------------- host --------------------------------------------
extern "C" void kernel_launch(void* const* d_in, const int* in_sizes, int n_in,
                              void* d_out, int out_size) {
    const float* x    = (const float*)d_in[0];
    const float* emb  = (const float*)d_in[1];
    const float* W_ih = (const float*)d_in[2];
    const float* W_hh = (const float*)d_in[3];
    const float* b_ih = (const float*)d_in[4];
    const float* b_hh = (const float*)d_in[5];
    const float* Wp   = (const float*)d_in[6];
    const float* bp   = (const float*)d_in[7];

    const size_t WSTRIDE = 4 * H_ * H_;
    const size_t BSTRIDE = 4 * H_;

    k_init_combo<<<1536, 256>>>(x, Wp, emb, W_ih, b_ih, b_hh);
    k_init_lstm_all<<<B_, 256>>>(x, W_ih, b_ih, b_hh);
    k_ghh0_init<<<dim3(8, 16), 256>>>(W_hh);   // Ghh0 from init h0

    for (int t = 0; t < T_STEPS; t++) {
        int rb = t & 1;
        int t_next = (t + 1 < T_STEPS) ? (t + 1) : (T_STEPS - 1);
        k_proj<<<B_, 256>>>(bp, t, rb);   // includes fused LSTM-0 epilogue
        k_lstm<1><<<dim3(8, 16), 256>>>(W_ih + 1 * WSTRIDE, W_hh + 1 * WSTRIDE,
                                        b_ih + 1 * BSTRIDE, b_hh + 1 * BSTRIDE,
                                        x, rb, t_next, W_hh);
        k_lstm<2><<<dim3(8, 32), 256>>>(W_ih + 2 * WSTRIDE, W_hh + 2 * WSTRIDE,
                                        b_ih + 2 * BSTRIDE, b_hh + 2 * BSTRIDE,
                                        x, rb, t_next, W_hh);   // y>=16: Ghh0(t+1)
    }
    k_out<<<(out_size + 255) / 256, 256>>>((float*)d_out, out_size);
}

// round 17
// speedup vs baseline: 1.5394x; 1.0104x over previous
#include <cuda_runtime.h>
#include <math.h>

#define T_STEPS 64
#define B_ 128
#define H_ 256
#define C_ 256
#define K_ 8
#define L_ 3
#define BK 1024
#define NEGV (-1e30f)

// ------------------------- device scratch (static, no allocs) ---------------
__device__ float g_WpT[H_ * C_];            // Wp transposed: [i][c]
__device__ float g_P0[C_ * 4 * H_];         // emb @ W_ih0^T + b_ih0 + b_hh0
__device__ float g_Ghh0[BK * 1024];         // h0 @ Whh0^T (ungathered), [row][j*4+gate]
__device__ float g_logits[BK * C_];         // state @ Wp^T + bp
__device__ float g_state[BK * H_];          // [B*K, H]
__device__ float g_h[2][L_][BK * H_];       // ping-pong hidden
__device__ float g_c[2][L_][BK * H_];       // ping-pong cell
__device__ float g_prefix[B_ * K_];
__device__ int   g_choices[B_ * K_ * T_STEPS];
__device__ int   g_src[BK];                 // gather source row (b*K + prev)
__device__ int   g_cls[BK];                 // chosen class per new beam row

// ------------------------- f32x2 packed helpers (sm_103a FFMA2) -------------
typedef unsigned long long u64;

__device__ __forceinline__ u64 fma2(u64 a, u64 b, u64 c) {
    u64 d;
    asm("fma.rn.f32x2 %0, %1, %2, %3;" : "=l"(d) : "l"(a), "l"(b), "l"(c));
    return d;
}
__device__ __forceinline__ u64 bcast2(float x) {
    u64 d; unsigned xi = __float_as_uint(x);
    asm("mov.b64 %0, {%1, %1};" : "=l"(d) : "r"(xi));
    return d;
}
__device__ __forceinline__ float lo2(u64 v) { return __uint_as_float((unsigned)v); }
__device__ __forceinline__ float hi2(u64 v) { return __uint_as_float((unsigned)(v >> 32)); }

// ------------------------- precise, fast-math-immune transcendentals --------
__device__ __forceinline__ float f_exp(float x) {
    const float LOG2E  = 1.4426950408889634f;
    const float LN2_HI = 0.693145751953125f;
    const float LN2_LO = 1.4286067653e-06f;
    float n = rintf(x * LOG2E);
    float r = fmaf(-n, LN2_HI, x);
    r = fmaf(-n, LN2_LO, r);
    float p = 1.9841269841e-4f;
    p = fmaf(p, r, 1.3888888889e-3f);
    p = fmaf(p, r, 8.3333333333e-3f);
    p = fmaf(p, r, 4.1666666667e-2f);
    p = fmaf(p, r, 1.6666666667e-1f);
    p = fmaf(p, r, 0.5f);
    p = fmaf(p, r, 1.0f);
    p = fmaf(p, r, 1.0f);
    int ni = (int)n;
    if (ni < -250) return 0.0f;
    if (ni >  250) ni = 250;
    int e1 = ni >> 1;
    int e2 = ni - e1;
    float s1 = __int_as_float((e1 + 127) << 23);
    float s2 = __int_as_float((e2 + 127) << 23);
    return p * s1 * s2;
}

__device__ __forceinline__ float f_tanh(float x) {
    float ax = fabsf(x);
    float t;
    if (ax < 0.25f) {
        float x2 = ax * ax;
        float p = 2.1869488536e-2f;
        p = fmaf(p, x2, -5.3968253968e-2f);
        p = fmaf(p, x2, 1.3333333333e-1f);
        p = fmaf(p, x2, -3.3333333333e-1f);
        t = fmaf(p * x2, ax, ax);
    } else {
        float e = f_exp(2.0f * ax);
        t = 1.0f - __fdiv_rn(2.0f, e + 1.0f);
    }
    return copysignf(t, x);
}

__device__ __forceinline__ float f_sig(float x) {
    return __fdiv_rn(1.0f, 1.0f + f_exp(-x));
}

// ------------------------- fused init: transpose + misc + P0 ----------------
__global__ __launch_bounds__(256) void k_init_combo(const float* __restrict__ x,
                                                    const float* __restrict__ Wp,
                                                    const float* __restrict__ emb,
                                                    const float* __restrict__ Wih0,
                                                    const float* __restrict__ bih0,
                                                    const float* __restrict__ bhh0) {
    int blk = blockIdx.x;
    if (blk < 1024) {
        int idx = blk * 256 + threadIdx.x;   // BK*H_ total
        int row = idx >> 8;
        int j = idx & 255;
        int b = row >> 3;
        g_state[idx] = x[b * H_ + j];
        if (idx < B_ * K_) g_prefix[idx] = ((idx & 7) == 0) ? 0.f : NEGV;
        if (idx < B_ * K_ * T_STEPS) g_choices[idx] = 0;
        return;
    }
    if (blk < 1280) {
        int idx = (blk - 1024) * 256 + threadIdx.x;   // H_*C_ total
        int i = idx >> 8, c = idx & 255;
        g_WpT[i * C_ + c] = Wp[c * H_ + i];
        return;
    }
    __shared__ float se[H_];
    int cidx = blk - 1280;
    se[threadIdx.x] = emb[cidx * H_ + threadIdx.x];
    __syncthreads();
    int t = threadIdx.x;
#pragma unroll
    for (int q = 0; q < 4; q++) {
        int n = q * H_ + t;
        const float4* wr = (const float4*)(Wih0 + (size_t)n * H_);
        float acc = 0.f;
#pragma unroll 8
        for (int k4 = 0; k4 < H_ / 4; k4++) {
            float4 w = wr[k4];
            float4 e = *(const float4*)&se[k4 * 4];
            acc += w.x * e.x + w.y * e.y + w.z * e.z + w.w * e.w;
        }
        g_P0[(size_t)cidx * (4 * H_) + n] = acc + bih0[n] + bhh0[n];
    }
}

// ------------------------- init LSTM, all 3 layers in one kernel ------------
__global__ __launch_bounds__(256) void k_init_lstm_all(const float* __restrict__ x,
                                                       const float* __restrict__ W_ih,
                                                       const float* __restrict__ b_ih,
                                                       const float* __restrict__ b_hh) {
    __shared__ float si[H_];
    int b = blockIdx.x;
    int t = threadIdx.x;
    const int WSTR = 4 * H_ * H_;
    const int BSTR = 4 * H_;
    for (int layer = 0; layer < L_; layer++) {
        const float* Wih = W_ih + (size_t)layer * WSTR;
        const float* bih = b_ih + (size_t)layer * BSTR;
        const float* bhh = b_hh + (size_t)layer * BSTR;
        const float* in = (layer == 0) ? (x + (size_t)b * H_)
                                       : (&g_h[0][layer - 1][0] + (size_t)(b * K_) * H_);
        si[t] = in[t];
        __syncthreads();
        float g4[4];
#pragma unroll
        for (int q = 0; q < 4; q++) {
            int n = q * H_ + t;
            const float4* wr = (const float4*)(Wih + (size_t)n * H_);
            float acc = 0.f;
#pragma unroll 8
            for (int k4 = 0; k4 < H_ / 4; k4++) {
                float4 w = wr[k4];
                float4 e = *(const float4*)&si[k4 * 4];
                acc += w.x * e.x + w.y * e.y + w.z * e.z + w.w * e.w;
            }
            g4[q] = acc + bih[n] + bhh[n];
        }
        float cn = f_sig(g4[0]) * f_tanh(g4[2]);
        float hn = f_sig(g4[3]) * f_tanh(cn);
#pragma unroll
        for (int kb = 0; kb < K_; kb++) {
            g_h[0][layer][((size_t)b * K_ + kb) * H_ + t] = hn;
            g_c[0][layer][((size_t)b * K_ + kb) * H_ + t] = cn;
        }
        __syncthreads();
    }
}

// ------------------------- Ghh0 GEMM body (bit-exact old-L0 chain) ----------
#define GHH0_BODY(H0PTR, WHH0, RBASE, JB)                                        \
    {                                                                            \
        int arow = tid >> 1;                                                     \
        int akq  = (tid & 1) * 16;                                               \
        int wrow = tid >> 2;                                                     \
        int wkq  = (tid & 3) * 8;                                                \
        const float* aHid = (H0PTR) + (size_t)((RBASE) + arow) * H_;             \
        const size_t wgrow = (size_t)((wrow & 3) * H_ + (JB) + (wrow >> 2)) * H_;\
        const float* whP = (WHH0) + wgrow;                                       \
        int tx = tid & 15, ty = tid >> 4;                                        \
        u64 acc[8][2];                                                           \
        _Pragma("unroll")                                                        \
        for (int r = 0; r < 8; r++) { acc[r][0] = 0ull; acc[r][1] = 0ull; }      \
        float4 a0, a1, a2, a3, w0, w1;                                           \
        {                                                                        \
            const float* p = aHid + akq;                                         \
            a0 = *(const float4*)p;       a1 = *(const float4*)(p + 4);          \
            a2 = *(const float4*)(p + 8); a3 = *(const float4*)(p + 12);         \
            const float* q = whP + wkq;                                          \
            w0 = *(const float4*)q; w1 = *(const float4*)(q + 4);                \
        }                                                                        \
        As[0][akq + 0][arow]  = a0.x; As[0][akq + 1][arow]  = a0.y;              \
        As[0][akq + 2][arow]  = a0.z; As[0][akq + 3][arow]  = a0.w;              \
        As[0][akq + 4][arow]  = a1.x; As[0][akq + 5][arow]  = a1.y;              \
        As[0][akq + 6][arow]  = a1.z; As[0][akq + 7][arow]  = a1.w;              \
        As[0][akq + 8][arow]  = a2.x; As[0][akq + 9][arow]  = a2.y;              \
        As[0][akq + 10][arow] = a2.z; As[0][akq + 11][arow] = a2.w;              \
        As[0][akq + 12][arow] = a3.x; As[0][akq + 13][arow] = a3.y;              \
        As[0][akq + 14][arow] = a3.z; As[0][akq + 15][arow] = a3.w;              \
        Ws[0][wkq + 0][wrow] = w0.x; Ws[0][wkq + 1][wrow] = w0.y;                \
        Ws[0][wkq + 2][wrow] = w0.z; Ws[0][wkq + 3][wrow] = w0.w;                \
        Ws[0][wkq + 4][wrow] = w1.x; Ws[0][wkq + 5][wrow] = w1.y;                \
        Ws[0][wkq + 6][wrow] = w1.z; Ws[0][wkq + 7][wrow] = w1.w;                \
        __syncthreads();                                                         \
        for (int kt = 0; kt < 8; kt++) {                                         \
            int buf = kt & 1;                                                    \
            bool more = (kt + 1 < 8);                                            \
            if (more) {                                                          \
                const float* p = aHid + (kt + 1) * 32 + akq;                     \
                a0 = *(const float4*)p;       a1 = *(const float4*)(p + 4);      \
                a2 = *(const float4*)(p + 8); a3 = *(const float4*)(p + 12);     \
                const float* q = whP + (kt + 1) * 32 + wkq;                      \
                w0 = *(const float4*)q; w1 = *(const float4*)(q + 4);            \
            }                                                                    \
            _Pragma("unroll")                                                    \
            for (int kk = 0; kk < 32; kk++) {                                    \
                float4 av0 = *(const float4*)&As[buf][kk][ty * 8];               \
                float4 av1 = *(const float4*)&As[buf][kk][ty * 8 + 4];           \
                ulonglong2 wv = *(const ulonglong2*)&Ws[buf][kk][tx * 4];        \
                u64 bb;                                                          \
                bb = bcast2(av0.x); acc[0][0] = fma2(bb, wv.x, acc[0][0]); acc[0][1] = fma2(bb, wv.y, acc[0][1]); \
                bb = bcast2(av0.y); acc[1][0] = fma2(bb, wv.x, acc[1][0]); acc[1][1] = fma2(bb, wv.y, acc[1][1]); \
                bb = bcast2(av0.z); acc[2][0] = fma2(bb, wv.x, acc[2][0]); acc[2][1] = fma2(bb, wv.y, acc[2][1]); \
                bb = bcast2(av0.w); acc[3][0] = fma2(bb, wv.x, acc[3][0]); acc[3][1] = fma2(bb, wv.y, acc[3][1]); \
                bb = bcast2(av1.x); acc[4][0] = fma2(bb, wv.x, acc[4][0]); acc[4][1] = fma2(bb, wv.y, acc[4][1]); \
                bb = bcast2(av1.y); acc[5][0] = fma2(bb, wv.x, acc[5][0]); acc[5][1] = fma2(bb, wv.y, acc[5][1]); \
                bb = bcast2(av1.z); acc[6][0] = fma2(bb, wv.x, acc[6][0]); acc[6][1] = fma2(bb, wv.y, acc[6][1]); \
                bb = bcast2(av1.w); acc[7][0] = fma2(bb, wv.x, acc[7][0]); acc[7][1] = fma2(bb, wv.y, acc[7][1]); \
            }                                                                    \
            if (more) {                                                          \
                int nb = buf ^ 1;                                                \
                As[nb][akq + 0][arow]  = a0.x; As[nb][akq + 1][arow]  = a0.y;    \
                As[nb][akq + 2][arow]  = a0.z; As[nb][akq + 3][arow]  = a0.w;    \
                As[nb][akq + 4][arow]  = a1.x; As[nb][akq + 5][arow]  = a1.y;    \
                As[nb][akq + 6][arow]  = a1.z; As[nb][akq + 7][arow]  = a1.w;    \
                As[nb][akq + 8][arow]  = a2.x; As[nb][akq + 9][arow]  = a2.y;    \
                As[nb][akq + 10][arow] = a2.z; As[nb][akq + 11][arow] = a2.w;    \
                As[nb][akq + 12][arow] = a3.x; As[nb][akq + 13][arow] = a3.y;    \
                As[nb][akq + 14][arow] = a3.z; As[nb][akq + 15][arow] = a3.w;    \
                Ws[nb][wkq + 0][wrow] = w0.x; Ws[nb][wkq + 1][wrow] = w0.y;      \
                Ws[nb][wkq + 2][wrow] = w0.z; Ws[nb][wkq + 3][wrow] = w0.w;      \
                Ws[nb][wkq + 4][wrow] = w1.x; Ws[nb][wkq + 5][wrow] = w1.y;      \
                Ws[nb][wkq + 6][wrow] = w1.z; Ws[nb][wkq + 7][wrow] = w1.w;      \
            }                                                                    \
            __syncthreads();                                                     \
        }                                                                        \
        _Pragma("unroll")                                                        \
        for (int r = 0; r < 8; r++) {                                            \
            int row = (RBASE) + ty * 8 + r;                                      \
            float4 v;                                                            \
            v.x = lo2(acc[r][0]); v.y = hi2(acc[r][0]);                          \
            v.z = lo2(acc[r][1]); v.w = hi2(acc[r][1]);                          \
            *(float4*)&g_Ghh0[(size_t)row * 1024 + ((JB) + tx) * 4] = v;         \
        }                                                                        \
    }

// ------------------------- standalone Ghh0 (for t=0, from init h) ------------
__global__ __launch_bounds__(256) void k_ghh0_init(const float* __restrict__ Whh0) {
    __shared__ __align__(16) float As[2][32][128];
    __shared__ __align__(16) float Ws[2][32][64];
    int tid = threadIdx.x;
    const float* h0 = &g_h[0][0][0];
    GHH0_BODY(h0, Whh0, blockIdx.x * 128, blockIdx.y * 16)
}

// ------------------------- logits GEMM (parallel; bit-exact chains) ---------
// Block = 4 beam-rows x all 256 classes; thread c computes 4 logits.
// Per-output chain: i ascending in groups of 4 with weights w0..w3 -> the
// exact FFMA order of the old k_proj GEMM. +bp at the end, same as before.
__global__ __launch_bounds__(256) void k_logits(const float* __restrict__ bp) {
    __shared__ __align__(16) float s_st[4][H_];
    int rg = blockIdx.x;            // 0..255: rows rg*4 .. rg*4+3
    int tid = threadIdx.x;
    int c = tid;
    for (int u = tid; u < 4 * H_; u += 256) {
        int r = u >> 8, i = u & 255;
        s_st[r][i] = g_state[(size_t)(rg * 4 + r) * H_ + i];
    }
    __syncthreads();
    float acc0 = 0.f, acc1 = 0.f, acc2 = 0.f, acc3 = 0.f;
    for (int i0 = 0; i0 < H_; i0 += 4) {
        float4 s0 = *(const float4*)&s_st[0][i0];
        float4 s1 = *(const float4*)&s_st[1][i0];
        float4 s2 = *(const float4*)&s_st[2][i0];
        float4 s3 = *(const float4*)&s_st[3][i0];
        float w0 = g_WpT[(i0 + 0) * C_ + c];
        float w1 = g_WpT[(i0 + 1) * C_ + c];
        float w2 = g_WpT[(i0 + 2) * C_ + c];
        float w3 = g_WpT[(i0 + 3) * C_ + c];
        acc0 = fmaf(s0.x, w0, acc0); acc0 = fmaf(s0.y, w1, acc0);
        acc0 = fmaf(s0.z, w2, acc0); acc0 = fmaf(s0.w, w3, acc0);
        acc1 = fmaf(s1.x, w0, acc1); acc1 = fmaf(s1.y, w1, acc1);
        acc1 = fmaf(s1.z, w2, acc1); acc1 = fmaf(s1.w, w3, acc1);
        acc2 = fmaf(s2.x, w0, acc2); acc2 = fmaf(s2.y, w1, acc2);
        acc2 = fmaf(s2.z, w2, acc2); acc2 = fmaf(s2.w, w3, acc2);
        acc3 = fmaf(s3.x, w0, acc3); acc3 = fmaf(s3.y, w1, acc3);
        acc3 = fmaf(s3.z, w2, acc3); acc3 = fmaf(s3.w, w3, acc3);
    }
    float bb = bp[c];
    g_logits[(size_t)(rg * 4 + 0) * C_ + c] = acc0 + bb;
    g_logits[(size_t)(rg * 4 + 1) * C_ + c] = acc1 + bb;
    g_logits[(size_t)(rg * 4 + 2) * C_ + c] = acc2 + bb;
    g_logits[(size_t)(rg * 4 + 3) * C_ + c] = acc3 + bb;
}

// ------------------- top-K + bookkeeping + fused LSTM-0 epilogue -------------
__global__ __launch_bounds__(256) void k_topk(int t, int rb) {
    __shared__ float s_pref[K_];
    __shared__ float s_red[8][K_];
    __shared__ float s_max[K_];
    __shared__ float s_lsum[K_];
    __shared__ float s_redv[8];
    __shared__ int   s_redi[8];
    __shared__ float s_topv[K_];
    __shared__ int   s_topi[K_];
    __shared__ int   s_prev[K_];
    __shared__ int   s_clss[K_];
    __shared__ int   s_ch[K_ * T_STEPS];

    int b = blockIdx.x;
    int tid = threadIdx.x;
    int warp = tid >> 5, lane = tid & 31;

    if (tid < K_) s_pref[tid] = g_prefix[b * K_ + tid];
    __syncthreads();

    int c = tid;
    float acc[K_];
#pragma unroll
    for (int k = 0; k < K_; k++)
        acc[k] = g_logits[(size_t)(b * K_ + k) * C_ + c];

    // per-beam max
    {
        float m[K_];
#pragma unroll
        for (int k = 0; k < K_; k++) {
            float v = acc[k];
            for (int o = 16; o; o >>= 1) v = fmaxf(v, __shfl_xor_sync(0xffffffffu, v, o));
            m[k] = v;
        }
        if (lane == 0)
#pragma unroll
            for (int k = 0; k < K_; k++) s_red[warp][k] = m[k];
        __syncthreads();
        if (tid < K_) {
            float v = s_red[0][tid];
            for (int w2 = 1; w2 < 8; w2++) v = fmaxf(v, s_red[w2][tid]);
            s_max[tid] = v;
        }
        __syncthreads();
    }
    float mx[K_];
#pragma unroll
    for (int k = 0; k < K_; k++) mx[k] = s_max[k];
    // per-beam sum of exp (precise exp)
    {
        float s[K_];
#pragma unroll
        for (int k = 0; k < K_; k++) {
            float v = f_exp(acc[k] - mx[k]);
            for (int o = 16; o; o >>= 1) v += __shfl_xor_sync(0xffffffffu, v, o);
            s[k] = v;
        }
        __syncthreads();
        if (lane == 0)
#pragma unroll
            for (int k = 0; k < K_; k++) s_red[warp][k] = s[k];
        __syncthreads();
        if (tid < K_) {
            float v = 0.f;
            for (int w2 = 0; w2 < 8; w2++) v += s_red[w2][tid];
            s_lsum[tid] = (float)log((double)v);   // precise log
        }
        __syncthreads();
    }
    float jt[K_];
#pragma unroll
    for (int k = 0; k < K_; k++) jt[k] = s_pref[k] + ((acc[k] - mx[k]) - s_lsum[k]);

    // iterated block argmax (ties -> lowest flat idx, matching jax top_k)
    for (int it = 0; it < K_; it++) {
        float bv = -INFINITY;
        int bi = 0x7fffffff;
#pragma unroll
        for (int k = 0; k < K_; k++) {
            if (jt[k] > bv) { bv = jt[k]; bi = k * C_ + c; }
        }
        for (int o = 16; o; o >>= 1) {
            float ov = __shfl_xor_sync(0xffffffffu, bv, o);
            int   oi = __shfl_xor_sync(0xffffffffu, bi, o);
            if (ov > bv || (ov == bv && oi < bi)) { bv = ov; bi = oi; }
        }
        if (lane == 0) { s_redv[warp] = bv; s_redi[warp] = bi; }
        __syncthreads();
        if (tid == 0) {
            float fv = s_redv[0]; int fi = s_redi[0];
            for (int w2 = 1; w2 < 8; w2++)
                if (s_redv[w2] > fv || (s_redv[w2] == fv && s_redi[w2] < fi)) {
                    fv = s_redv[w2]; fi = s_redi[w2];
                }
            s_topv[it] = fv; s_topi[it] = fi;
        }
        __syncthreads();
        int sel = s_topi[it];
        if ((sel & (C_ - 1)) == c) jt[sel >> 8] = -INFINITY;
    }

    if (tid < K_) {
        int sel = s_topi[tid];
        int prev = sel >> 8;
        int cls = sel & (C_ - 1);
        g_prefix[b * K_ + tid] = s_topv[tid];
        g_src[b * K_ + tid] = b * K_ + prev;
        g_cls[b * K_ + tid] = cls;
        s_prev[tid] = prev;
        s_clss[tid] = cls;
    }
    __syncthreads();
    for (int u = tid; u < K_ * T_STEPS; u += 256) {
        int kq = u >> 6, tt = u & 63;
        s_ch[u] = g_choices[(b * K_ + s_prev[kq]) * T_STEPS + tt];
    }
    __syncthreads();
    for (int u = tid; u < K_ * T_STEPS; u += 256) {
        int kq = u >> 6, tt = u & 63;
        g_choices[(b * K_ + kq) * T_STEPS + tt] = (tt == t) ? s_clss[kq] : s_ch[u];
    }

    // ---- fused LSTM layer-0 epilogue (bit-exact: Ghh0 gather + P0 + gates) ----
    {
        int j = tid;                    // 0..255
        const float* c0cur = g_c[rb][0];
        float* h0nxt = g_h[1 - rb][0];
        float* c0nxt = g_c[1 - rb][0];
#pragma unroll
        for (int kb = 0; kb < K_; kb++) {
            int row = b * K_ + kb;
            int srcrow = b * K_ + s_prev[kb];
            float4 gv = *(const float4*)&g_Ghh0[(size_t)srcrow * 1024 + j * 4];
            const float* p0 = g_P0 + (size_t)s_clss[kb] * (4 * H_);
            float gi = gv.x; gi += p0[0 * H_ + j];
            float gf = gv.y; gf += p0[1 * H_ + j];
            float gg = gv.z; gg += p0[2 * H_ + j];
            float go = gv.w; go += p0[3 * H_ + j];
            float cold = c0cur[(size_t)srcrow * H_ + j];
            float cn = f_sig(gf) * cold + f_sig(gi) * f_tanh(gg);
            float hn = f_sig(go) * f_tanh(cn);
            c0nxt[(size_t)row * H_ + j] = cn;
            h0nxt[(size_t)row * H_ + j] = hn;
        }
    }
}

// ------------------------- LSTM layer GEMM + gates (layers 1,2) -------------
template <int LAYER>
__global__ __launch_bounds__(256) void k_lstm(const float* __restrict__ Wih,
                                              const float* __restrict__ Whh,
                                              const float* __restrict__ bih,
                                              const float* __restrict__ bhh,
                                              const float* __restrict__ x,
                                              int rb, int t_next,
                                              const float* __restrict__ Whh0) {
    __shared__ __align__(16) float As[2][32][128];
    __shared__ __align__(16) float Ws[2][32][64];
    __shared__ int s_src[128];

    int tid = threadIdx.x;
    int rBase = blockIdx.x * 128;

    if (LAYER == 2 && blockIdx.y >= 16) {
        const float* h0 = &g_h[1 - rb][0][0];
        GHH0_BODY(h0, Whh0, rBase, (int)(blockIdx.y - 16) * 16)
        return;
    }

    const float* hcur = g_h[rb][LAYER];
    const float* ccur = g_c[rb][LAYER];
    float* hnxt = g_h[1 - rb][LAYER];
    float* cnxt = g_c[1 - rb][LAYER];
    const float* inp = g_h[1 - rb][LAYER - 1];

    int jBase = blockIdx.y * 16;

    if (tid < 128) s_src[tid] = g_src[rBase + tid];
    __syncthreads();

    int arow = tid >> 1;
    int akq  = (tid & 1) * 16;
    int wrow = tid >> 2;
    int wkq  = (tid & 3) * 8;

    const float* aHid = hcur + (size_t)s_src[arow] * H_;
    const float* aIn  = inp + (size_t)(rBase + arow) * H_;
    const size_t wgrow = (size_t)((wrow & 3) * H_ + jBase + (wrow >> 2)) * H_;
    const float* wiP = Wih + wgrow;
    const float* whP = Whh + wgrow;

    const int NT = 16;   // K=512 / 32

    int tx = tid & 15, ty = tid >> 4;

    u64 acc[8][2];
#pragma unroll
    for (int r = 0; r < 8; r++) { acc[r][0] = 0ull; acc[r][1] = 0ull; }

    float4 a0, a1, a2, a3, w0, w1;
    {
        int k = akq;
        const float* p = (k < 256) ? (aIn + k) : (aHid + (k - 256));
        a0 = *(const float4*)p;       a1 = *(const float4*)(p + 4);
        a2 = *(const float4*)(p + 8); a3 = *(const float4*)(p + 12);
        int kw = wkq;
        const float* q = (kw < 256) ? (wiP + kw) : (whP + (kw - 256));
        w0 = *(const float4*)q; w1 = *(const float4*)(q + 4);
    }
    {
        As[0][akq + 0][arow]  = a0.x; As[0][akq + 1][arow]  = a0.y;
        As[0][akq + 2][arow]  = a0.z; As[0][akq + 3][arow]  = a0.w;
        As[0][akq + 4][arow]  = a1.x; As[0][akq + 5][arow]  = a1.y;
        As[0][akq + 6][arow]  = a1.z; As[0][akq + 7][arow]  = a1.w;
        As[0][akq + 8][arow]  = a2.x; As[0][akq + 9][arow]  = a2.y;
        As[0][akq + 10][arow] = a2.z; As[0][akq + 11][arow] = a2.w;
        As[0][akq + 12][arow] = a3.x; As[0][akq + 13][arow] = a3.y;
        As[0][akq + 14][arow] = a3.z; As[0][akq + 15][arow] = a3.w;
        Ws[0][wkq + 0][wrow] = w0.x; Ws[0][wkq + 1][wrow] = w0.y;
        Ws[0][wkq + 2][wrow] = w0.z; Ws[0][wkq + 3][wrow] = w0.w;
        Ws[0][wkq + 4][wrow] = w1.x; Ws[0][wkq + 5][wrow] = w1.y;
        Ws[0][wkq + 6][wrow] = w1.z; Ws[0][wkq + 7][wrow] = w1.w;
    }
    __syncthreads();

    for (int kt = 0; kt < NT; kt++) {
        int buf = kt & 1;
        bool more = (kt + 1 < NT);
        if (more) {
            int k = (kt + 1) * 32 + akq;
            const float* p = (k < 256) ? (aIn + k) : (aHid + (k - 256));
            a0 = *(const float4*)p;       a1 = *(const float4*)(p + 4);
            a2 = *(const float4*)(p + 8); a3 = *(const float4*)(p + 12);
            int kw = (kt + 1) * 32 + wkq;
            const float* q = (kw < 256) ? (wiP + kw) : (whP + (kw - 256));
            w0 = *(const float4*)q; w1 = *(const float4*)(q + 4);
        }
#pragma unroll
        for (int kk = 0; kk < 32; kk++) {
            float4 av0 = *(const float4*)&As[buf][kk][ty * 8];
            float4 av1 = *(const float4*)&As[buf][kk][ty * 8 + 4];
            ulonglong2 wv = *(const ulonglong2*)&Ws[buf][kk][tx * 4];
            u64 bb;
            bb = bcast2(av0.x); acc[0][0] = fma2(bb, wv.x, acc[0][0]); acc[0][1] = fma2(bb, wv.y, acc[0][1]);
            bb = bcast2(av0.y); acc[1][0] = fma2(bb, wv.x, acc[1][0]); acc[1][1] = fma2(bb, wv.y, acc[1][1]);
            bb = bcast2(av0.z); acc[2][0] = fma2(bb, wv.x, acc[2][0]); acc[2][1] = fma2(bb, wv.y, acc[2][1]);
            bb = bcast2(av0.w); acc[3][0] = fma2(bb, wv.x, acc[3][0]); acc[3][1] = fma2(bb, wv.y, acc[3][1]);
            bb = bcast2(av1.x); acc[4][0] = fma2(bb, wv.x, acc[4][0]); acc[4][1] = fma2(bb, wv.y, acc[4][1]);
            bb = bcast2(av1.y); acc[5][0] = fma2(bb, wv.x, acc[5][0]); acc[5][1] = fma2(bb, wv.y, acc[5][1]);
            bb = bcast2(av1.z); acc[6][0] = fma2(bb, wv.x, acc[6][0]); acc[6][1] = fma2(bb, wv.y, acc[6][1]);
            bb = bcast2(av1.w); acc[7][0] = fma2(bb, wv.x, acc[7][0]); acc[7][1] = fma2(bb, wv.y, acc[7][1]);
        }
        if (more) {
            int nb = buf ^ 1;
            As[nb][akq + 0][arow]  = a0.x; As[nb][akq + 1][arow]  = a0.y;
            As[nb][akq + 2][arow]  = a0.z; As[nb][akq + 3][arow]  = a0.w;
            As[nb][akq + 4][arow]  = a1.x; As[nb][akq + 5][arow]  = a1.y;
            As[nb][akq + 6][arow]  = a1.z; As[nb][akq + 7][arow]  = a1.w;
            As[nb][akq + 8][arow]  = a2.x; As[nb][akq + 9][arow]  = a2.y;
            As[nb][akq + 10][arow] = a2.z; As[nb][akq + 11][arow] = a2.w;
            As[nb][akq + 12][arow] = a3.x; As[nb][akq + 13][arow] = a3.y;
            As[nb][akq + 14][arow] = a3.z; As[nb][akq + 15][arow] = a3.w;
            Ws[nb][wkq + 0][wrow] = w0.x; Ws[nb][wkq + 1][wrow] = w0.y;
            Ws[nb][wkq + 2][wrow] = w0.z; Ws[nb][wkq + 3][wrow] = w0.w;
            Ws[nb][wkq + 4][wrow] = w1.x; Ws[nb][wkq + 5][wrow] = w1.y;
            Ws[nb][wkq + 6][wrow] = w1.z; Ws[nb][wkq + 7][wrow] = w1.w;
        }
        __syncthreads();
    }

    int j = jBase + tx;
    float bias[4];
#pragma unroll
    for (int q = 0; q < 4; q++) bias[q] = bih[q * H_ + j] + bhh[q * H_ + j];
#pragma unroll
    for (int r = 0; r < 8; r++) {
        int rl = ty * 8 + r;
        int row_g = rBase + rl;
        int b = row_g >> 3;
        float gi = lo2(acc[r][0]), gf = hi2(acc[r][0]);
        float gg = lo2(acc[r][1]), go = hi2(acc[r][1]);
        gi += bias[0]; gf += bias[1]; gg += bias[2]; go += bias[3];
        float cold = ccur[(size_t)s_src[rl] * H_ + j];
        float cn = f_sig(gf) * cold + f_sig(gi) * f_tanh(gg);
        float hn = f_sig(go) * f_tanh(cn);
        cnxt[(size_t)row_g * H_ + j] = cn;
        hnxt[(size_t)row_g * H_ + j] = hn;
        if (LAYER == 2)
            g_state[(size_t)row_g * H_ + j] = hn + x[(size_t)t_next * B_ * H_ + b * H_ + j];
    }
}

// ------------------------- output ------------------------------------------
__global__ void k_out(float* __restrict__ out, int n) {
    int i = blockIdx.x * 256 + threadIdx.x;
    if (i >= n) return;
    if (i < B_ * K_ * T_STEPS) out[i] = (float)g_choices[i];
    else if (i < B_ * K_ * T_STEPS + B_ * K_) out[i] = g_prefix[i - B_ * K_ * T_STEPS];
    else out[i] = 0.f;
}

// ------------------------- host --------------------------------------------
extern "C" void kernel_launch(void* const* d_in, const int* in_sizes, int n_in,
                              void* d_out, int out_size) {
    const float* x    = (const float*)d_in[0];
    const float* emb  = (const float*)d_in[1];
    const float* W_ih = (const float*)d_in[2];
    const float* W_hh = (const float*)d_in[3];
    const float* b_ih = (const float*)d_in[4];
    const float* b_hh = (const float*)d_in[5];
    const float* Wp   = (const float*)d_in[6];
    const float* bp   = (const float*)d_in[7];

    const size_t WSTRIDE = 4 * H_ * H_;
    const size_t BSTRIDE = 4 * H_;

    k_init_combo<<<1536, 256>>>(x, Wp, emb, W_ih, b_ih, b_hh);
    k_init_lstm_all<<<B_, 256>>>(x, W_ih, b_ih, b_hh);
    k_ghh0_init<<<dim3(8, 16), 256>>>(W_hh);   // Ghh0 from init h0

    for (int t = 0; t < T_STEPS; t++) {
        int rb = t & 1;
        int t_next = (t + 1 < T_STEPS) ? (t + 1) : (T_STEPS - 1);
        k_logits<<<256, 256>>>(bp);
        k_topk<<<B_, 256>>>(t, rb);       // includes fused LSTM-0 epilogue
        k_lstm<1><<<dim3(8, 16), 256>>>(W_ih + 1 * WSTRIDE, W_hh + 1 * WSTRIDE,
                                        b_ih + 1 * BSTRIDE, b_hh + 1 * BSTRIDE,
                                        x, rb, t_next, W_hh);
        k_lstm<2><<<dim3(8, 32), 256>>>(W_ih + 2 * WSTRIDE, W_hh + 2 * WSTRIDE,
                                        b_ih + 2 * BSTRIDE, b_hh + 2 * BSTRIDE,
                                        x, rb, t_next, W_hh);   // y>=16: Ghh0(t+1)
    }
    k_out<<<(out_size + 255) / 256, 256>>>((float*)d_out, out_size);
}